// round 7
// baseline (speedup 1.0000x reference)
#include <cuda_runtime.h>
#include <math.h>

#define N_NODES 8192
#define N_EDGES 65536
#define CDIM 64
#define NB 8
#define NELEM 10
#define NGRAPH 8

// Scratch (device globals; no allocation allowed)
__device__ float g_s[N_NODES * CDIM];
__device__ float g_m[N_NODES * CDIM];
__device__ float g_energy[N_NODES];
__device__ float g_ef[N_EDGES * NB];
__device__ int   g_elem[N_NODES];

// ---------------- packed f32x2 helpers (Blackwell FFMA2) -------------------
__device__ __forceinline__ unsigned long long pack2(float x, float y) {
    unsigned long long r;
    asm("mov.b64 %0, {%1, %2};" : "=l"(r) : "f"(x), "f"(y));
    return r;
}
__device__ __forceinline__ unsigned long long ffma2(unsigned long long a,
                                                    unsigned long long b,
                                                    unsigned long long c) {
    unsigned long long d;
    asm("fma.rn.f32x2 %0, %1, %2, %3;" : "=l"(d) : "l"(a), "l"(b), "l"(c));
    return d;
}
__device__ __forceinline__ float2 unpack2(unsigned long long v) {
    float x, y;
    asm("mov.b64 {%0, %1}, %2;" : "=f"(x), "=f"(y) : "l"(v));
    return make_float2(x, y);
}
__device__ __forceinline__ float silu(float x) {
    return __fdividef(x, 1.0f + __expf(-x));
}

// ---------------------------------------------------------------------------
__global__ void init_kernel(const float* __restrict__ node_attrs,
                            const float* __restrict__ atomic_energies,
                            const float* __restrict__ W_embed,
                            float* __restrict__ d_out) {
    int n = blockIdx.x * blockDim.x + threadIdx.x;
    if (n >= N_NODES) return;
    if (n < NGRAPH) d_out[n] = 0.0f;

    const float* row = node_attrs + n * NELEM;
    int el = 0;
#pragma unroll
    for (int k = 0; k < NELEM; k++)
        if (row[k] > 0.5f) el = k;
    g_elem[n] = el;
    g_energy[n] = atomic_energies[el];

    const float4* we = (const float4*)(W_embed + el * CDIM);
    float4* srow = (float4*)(g_s + n * CDIM);
    float4* mrow = (float4*)(g_m + n * CDIM);
#pragma unroll
    for (int q = 0; q < CDIM / 4; q++) {
        srow[q] = we[q];
        mrow[q] = make_float4(0.f, 0.f, 0.f, 0.f);
    }
}

// ---------------------------------------------------------------------------
// edge features for one edge (bessel * poly cutoff); sh[:,0]==1
// ---------------------------------------------------------------------------
__device__ __forceinline__ void compute_ef(const float* __restrict__ positions,
                                           int snd, int rcv, float* ef) {
    float dx = positions[rcv * 3 + 0] - positions[snd * 3 + 0];
    float dy = positions[rcv * 3 + 1] - positions[snd * 3 + 1];
    float dz = positions[rcv * 3 + 2] - positions[snd * 3 + 2];
    float r = sqrtf(dx * dx + dy * dy + dz * dz);
    float rs = fmaxf(r, 1e-9f);
    float t = r * 0.2f;
    if (t < 1.0f) {
        float t2 = t * t;
        float t5 = t2 * t2 * t;
        float env = 1.0f - 21.0f * t5 + 35.0f * t5 * t - 15.0f * t5 * t2;
        float scale = 0.6324555320336759f * env / rs;
        float x = 0.62831853071795864769f * rs;
        float s1, c1;
        __sincosf(x, &s1, &c1);
        float twoc = 2.0f * c1;
        float sm1 = 0.0f, sn = s1;
#pragma unroll
        for (int k = 0; k < NB; k++) {
            ef[k] = sn * scale;
            float nxt = twoc * sn - sm1;
            sm1 = sn; sn = nxt;
        }
    } else {
#pragma unroll
        for (int k = 0; k < NB; k++) ef[k] = 0.0f;
    }
}

// ---------------------------------------------------------------------------
// edge MLP: block = 256 threads = 8 warps; warp w owns output slice
// [w*8, w*8+8); thread (warp, lane g) processes 4 edges (block: 128 edges).
// One 16KB smem buffer holds W2 during layers 1-2, reloaded with W3 (l=0
// slice) before layer 3 — smem 51.7KB + <=64 regs => 4 blocks/SM, grid 512
// fits in ONE wave (592 capacity).
// ---------------------------------------------------------------------------
#define EPB 128

__global__ __launch_bounds__(256, 4) void edge_mlp_kernel(
    const float* __restrict__ w1, const float* __restrict__ b1,
    const float* __restrict__ w2, const float* __restrict__ b2,
    const float* __restrict__ w3, const int* __restrict__ edge_index,
    const float* __restrict__ positions, int first) {
    extern __shared__ float smp[];
    float* swb = smp;              // 4096 floats: W2, later W3
    float* act = smp + 4096;       // 8192 (transposed: [c][edge])
    float* sw1 = smp + 12288;      // 512
    float* sb1 = smp + 12800;      // 64
    float* sb2 = smp + 12864;      // 64

    int tid = threadIdx.x;
    for (int k = tid; k < 1024; k += 256)
        ((float4*)swb)[k] = ((const float4*)w2)[k];
    for (int k = tid; k < 128; k += 256)
        ((float4*)sw1)[k] = ((const float4*)w1)[k];
    if (tid < 64) { sb1[tid] = b1[tid]; sb2[tid] = b2[tid]; }

    int slice = tid >> 5;          // warp id = output slice
    int g = tid & 31;              // lane = edge group
    int s8 = slice * 8;
    int ebase = blockIdx.x * EPB + g * 4;

    // ---- edge features for 4 edges ----
    float ef[4][8];
    if (first) {
        int4 snd4 = *(const int4*)(edge_index + ebase);
        int4 rcv4 = *(const int4*)(edge_index + N_EDGES + ebase);
        const int* snds = &snd4.x;
        const int* rcvs = &rcv4.x;
#pragma unroll
        for (int e = 0; e < 4; e++) {
            compute_ef(positions, snds[e], rcvs[e], ef[e]);
            float4* out = (float4*)(g_ef + (ebase + e) * NB);
            out[0] = make_float4(ef[e][0], ef[e][1], ef[e][2], ef[e][3]);
            out[1] = make_float4(ef[e][4], ef[e][5], ef[e][6], ef[e][7]);
        }
    } else {
#pragma unroll
        for (int e = 0; e < 4; e++) {
            const float4* v = (const float4*)(g_ef + (ebase + e) * NB);
            float4 v0 = v[0], v1 = v[1];
            ef[e][0] = v0.x; ef[e][1] = v0.y; ef[e][2] = v0.z; ef[e][3] = v0.w;
            ef[e][4] = v1.x; ef[e][5] = v1.y; ef[e][6] = v1.z; ef[e][7] = v1.w;
        }
    }
    __syncthreads();

    // ---- layer 1: 8 -> 64 ----
    float a[4][8];
#pragma unroll
    for (int e = 0; e < 4; e++)
#pragma unroll
        for (int k = 0; k < 8; k++) a[e][k] = sb1[s8 + k];
#pragma unroll
    for (int c = 0; c < NB; c++) {
        float4 wa = *(const float4*)(sw1 + c * CDIM + s8);
        float4 wb = *(const float4*)(sw1 + c * CDIM + s8 + 4);
#pragma unroll
        for (int e = 0; e < 4; e++) {
            float x = ef[e][c];
            a[e][0] += x * wa.x; a[e][1] += x * wa.y;
            a[e][2] += x * wa.z; a[e][3] += x * wa.w;
            a[e][4] += x * wb.x; a[e][5] += x * wb.y;
            a[e][6] += x * wb.z; a[e][7] += x * wb.w;
        }
    }
#pragma unroll
    for (int k = 0; k < 8; k++) {
        float4 t = make_float4(silu(a[0][k]), silu(a[1][k]),
                               silu(a[2][k]), silu(a[3][k]));
        *(float4*)(act + (s8 + k) * EPB + g * 4) = t;
    }
    __syncthreads();

    // ---- layer 2: 64 -> 64 ----
    unsigned long long acc[4][4];
#pragma unroll
    for (int i = 0; i < 4; i++) {
        unsigned long long bi = pack2(sb2[s8 + 2 * i], sb2[s8 + 2 * i + 1]);
#pragma unroll
        for (int e = 0; e < 4; e++) acc[e][i] = bi;
    }
#pragma unroll 16
    for (int c = 0; c < CDIM; c++) {
        float4 av = *(const float4*)(act + c * EPB + g * 4);
        ulonglong2 wA = *(const ulonglong2*)(swb + c * CDIM + s8);
        ulonglong2 wB = *(const ulonglong2*)(swb + c * CDIM + s8 + 4);
        unsigned long long a0 = pack2(av.x, av.x);
        unsigned long long a1 = pack2(av.y, av.y);
        unsigned long long a2 = pack2(av.z, av.z);
        unsigned long long a3 = pack2(av.w, av.w);
        acc[0][0] = ffma2(a0, wA.x, acc[0][0]);
        acc[0][1] = ffma2(a0, wA.y, acc[0][1]);
        acc[0][2] = ffma2(a0, wB.x, acc[0][2]);
        acc[0][3] = ffma2(a0, wB.y, acc[0][3]);
        acc[1][0] = ffma2(a1, wA.x, acc[1][0]);
        acc[1][1] = ffma2(a1, wA.y, acc[1][1]);
        acc[1][2] = ffma2(a1, wB.x, acc[1][2]);
        acc[1][3] = ffma2(a1, wB.y, acc[1][3]);
        acc[2][0] = ffma2(a2, wA.x, acc[2][0]);
        acc[2][1] = ffma2(a2, wA.y, acc[2][1]);
        acc[2][2] = ffma2(a2, wB.x, acc[2][2]);
        acc[2][3] = ffma2(a2, wB.y, acc[2][3]);
        acc[3][0] = ffma2(a3, wA.x, acc[3][0]);
        acc[3][1] = ffma2(a3, wA.y, acc[3][1]);
        acc[3][2] = ffma2(a3, wB.x, acc[3][2]);
        acc[3][3] = ffma2(a3, wB.y, acc[3][3]);
    }
    __syncthreads();           // all reads of act AND swb(W2) done

    // reload swb with W3 (l=0 slice) while writing silu(act)
    for (int k = tid; k < 1024; k += 256) {
        int c = k >> 4, jq = k & 15;
        ((float4*)swb)[k] = ((const float4*)w3)[c * 64 + jq];
    }
#pragma unroll
    for (int i = 0; i < 4; i++) {
        float2 p0 = unpack2(acc[0][i]);
        float2 p1 = unpack2(acc[1][i]);
        float2 p2 = unpack2(acc[2][i]);
        float2 p3 = unpack2(acc[3][i]);
        float4 lo = make_float4(silu(p0.x), silu(p1.x), silu(p2.x), silu(p3.x));
        float4 hi = make_float4(silu(p0.y), silu(p1.y), silu(p2.y), silu(p3.y));
        *(float4*)(act + (s8 + 2 * i) * EPB + g * 4) = lo;
        *(float4*)(act + (s8 + 2 * i + 1) * EPB + g * 4) = hi;
    }
    __syncthreads();

    // ---- layer 3: 64 -> 64 (no bias/act) ----
#pragma unroll
    for (int e = 0; e < 4; e++)
#pragma unroll
        for (int i = 0; i < 4; i++) acc[e][i] = 0ull;
#pragma unroll 16
    for (int c = 0; c < CDIM; c++) {
        float4 av = *(const float4*)(act + c * EPB + g * 4);
        ulonglong2 wA = *(const ulonglong2*)(swb + c * CDIM + s8);
        ulonglong2 wB = *(const ulonglong2*)(swb + c * CDIM + s8 + 4);
        unsigned long long a0 = pack2(av.x, av.x);
        unsigned long long a1 = pack2(av.y, av.y);
        unsigned long long a2 = pack2(av.z, av.z);
        unsigned long long a3 = pack2(av.w, av.w);
        acc[0][0] = ffma2(a0, wA.x, acc[0][0]);
        acc[0][1] = ffma2(a0, wA.y, acc[0][1]);
        acc[0][2] = ffma2(a0, wB.x, acc[0][2]);
        acc[0][3] = ffma2(a0, wB.y, acc[0][3]);
        acc[1][0] = ffma2(a1, wA.x, acc[1][0]);
        acc[1][1] = ffma2(a1, wA.y, acc[1][1]);
        acc[1][2] = ffma2(a1, wB.x, acc[1][2]);
        acc[1][3] = ffma2(a1, wB.y, acc[1][3]);
        acc[2][0] = ffma2(a2, wA.x, acc[2][0]);
        acc[2][1] = ffma2(a2, wA.y, acc[2][1]);
        acc[2][2] = ffma2(a2, wB.x, acc[2][2]);
        acc[2][3] = ffma2(a2, wB.y, acc[2][3]);
        acc[3][0] = ffma2(a3, wA.x, acc[3][0]);
        acc[3][1] = ffma2(a3, wA.y, acc[3][1]);
        acc[3][2] = ffma2(a3, wB.x, acc[3][2]);
        acc[3][3] = ffma2(a3, wB.y, acc[3][3]);
    }

    // ---- message: msg = R0 * s[snd]; scatter to m[rcv] ----
    int4 snd4 = *(const int4*)(edge_index + ebase);
    int4 rcv4 = *(const int4*)(edge_index + N_EDGES + ebase);
    const int* snds = &snd4.x;
    const int* rcvs = &rcv4.x;
#pragma unroll
    for (int e = 0; e < 4; e++) {
        float o[8];
#pragma unroll
        for (int i = 0; i < 4; i++) {
            float2 p = unpack2(acc[e][i]);
            o[2 * i] = p.x; o[2 * i + 1] = p.y;
        }
        int snd = snds[e], rcv = rcvs[e];
        const float4* srow = (const float4*)(g_s + snd * CDIM + s8);
        float4 sv0 = srow[0], sv1 = srow[1];
        float* mrow = g_m + rcv * CDIM + s8;
        atomicAdd(mrow + 0, o[0] * sv0.x);
        atomicAdd(mrow + 1, o[1] * sv0.y);
        atomicAdd(mrow + 2, o[2] * sv0.z);
        atomicAdd(mrow + 3, o[3] * sv0.w);
        atomicAdd(mrow + 4, o[4] * sv1.x);
        atomicAdd(mrow + 5, o[5] * sv1.y);
        atomicAdd(mrow + 6, o[6] * sv1.z);
        atomicAdd(mrow + 7, o[7] * sv1.w);
    }
}

// ---------------------------------------------------------------------------
// node update: warp-per-node pair; 32 nodes/block.
// ---------------------------------------------------------------------------
#define NPB 32

__global__ __launch_bounds__(256) void node_kernel(
    const float* __restrict__ Wlin0,
    const float* __restrict__ Wprod,
    const float* __restrict__ Wsc,
    const float* __restrict__ Wread,
    const int* __restrict__ batch,
    float* __restrict__ d_out, int last) {
    __shared__ float swl[CDIM * CDIM];
    __shared__ float m_sm[NPB * CDIM];
    __shared__ float bins[NGRAPH];

    int tid = threadIdx.x;
    for (int k = tid; k < 1024; k += 256)
        ((float4*)swl)[k] = ((const float4*)Wlin0)[k];

    float4* gm = (float4*)(g_m + blockIdx.x * NPB * CDIM);
#pragma unroll
    for (int q = 0; q < 2; q++) {
        int idx = q * 256 + tid;
        float4 v = gm[idx];
        gm[idx] = make_float4(0.f, 0.f, 0.f, 0.f);
        ((float4*)m_sm)[idx] = make_float4(v.x * 0.125f, v.y * 0.125f,
                                           v.z * 0.125f, v.w * 0.125f);
    }
    if (tid < NGRAPH) bins[tid] = 0.0f;
    __syncthreads();

    int w = tid >> 5, g = tid & 31;
    int g2 = g * 2;

#pragma unroll
    for (int pair = 0; pair < 2; pair++) {
        int nl0 = w * 4 + pair * 2;
        const float* m0 = m_sm + nl0 * CDIM;
        const float* m1 = m0 + CDIM;
        unsigned long long acc0 = 0ull, acc1 = 0ull;
#pragma unroll 16
        for (int c = 0; c < CDIM; c++) {
            unsigned long long wv =
                *(const unsigned long long*)(swl + c * CDIM + g2);
            float av = m0[c], bv = m1[c];
            acc0 = ffma2(pack2(av, av), wv, acc0);
            acc1 = ffma2(pack2(bv, bv), wv, acc1);
        }
#pragma unroll
        for (int e = 0; e < 2; e++) {
            int node = blockIdx.x * NPB + nl0 + e;
            float2 f = unpack2(e ? acc1 : acc0);
            int el = g_elem[node];
            float2 w0 = *(const float2*)(Wprod + (0 * NELEM + el) * CDIM + g2);
            float2 w1 = *(const float2*)(Wprod + (1 * NELEM + el) * CDIM + g2);
            float2 w2 = *(const float2*)(Wprod + (2 * NELEM + el) * CDIM + g2);
            float2 sc = *(const float2*)(Wsc + el * CDIM + g2);
            float2 wr = *(const float2*)(Wread + g2);
            float2 sp = *(const float2*)(g_s + node * CDIM + g2);
            float hx = f.x * (w0.x + w1.x * f.x + w2.x * f.x * f.x) + sc.x * sp.x;
            float hy = f.y * (w0.y + w1.y * f.y + w2.y * f.y * f.y) + sc.y * sp.y;
            *(float2*)(g_s + node * CDIM + g2) = make_float2(hx, hy);
            float en = hx * wr.x + hy * wr.y;
#pragma unroll
            for (int off = 16; off > 0; off >>= 1)
                en += __shfl_down_sync(0xffffffffu, en, off);
            if (g == 0) {
                if (!last) g_energy[node] += en;
                else atomicAdd(&bins[batch[node]], g_energy[node] + en);
            }
        }
    }
    if (last) {
        __syncthreads();
        if (tid < NGRAPH) atomicAdd(d_out + tid, bins[tid]);
    }
}

// ---------------------------------------------------------------------------
extern "C" void kernel_launch(void* const* d_in, const int* in_sizes, int n_in,
                              void* d_out, int out_size) {
    const float* positions       = (const float*)d_in[0];
    const float* node_attrs      = (const float*)d_in[1];
    const int*   edge_index      = (const int*)d_in[2];
    const int*   batch           = (const int*)d_in[3];
    const float* atomic_energies = (const float*)d_in[4];
    const float* W_embed         = (const float*)d_in[5];
    const float* rw1             = (const float*)d_in[6];
    const float* rb1             = (const float*)d_in[7];
    const float* rw2             = (const float*)d_in[8];
    const float* rb2             = (const float*)d_in[9];
    const float* rw3             = (const float*)d_in[10];
    const float* Wlin            = (const float*)d_in[11];
    const float* Wprod           = (const float*)d_in[12];
    const float* Wsc             = (const float*)d_in[13];
    const float* Wread           = (const float*)d_in[14];
    float* out = (float*)d_out;

    const int EDGE_SMEM = 12928 * 4;   // 51712 B dynamic
    cudaFuncSetAttribute(edge_mlp_kernel,
                         cudaFuncAttributeMaxDynamicSharedMemorySize, EDGE_SMEM);

    init_kernel<<<N_NODES / 128, 128>>>(node_attrs, atomic_energies, W_embed, out);
    for (int i = 0; i < 2; i++) {
        edge_mlp_kernel<<<N_EDGES / EPB, 256, EDGE_SMEM>>>(
            rw1 + i * NB * CDIM, rb1 + i * CDIM,
            rw2 + i * CDIM * CDIM, rb2 + i * CDIM,
            rw3 + i * CDIM * 4 * CDIM, edge_index, positions, i == 0 ? 1 : 0);
        node_kernel<<<N_NODES / NPB, 256>>>(
            Wlin + i * 4 * CDIM * CDIM,
            Wprod + i * 3 * NELEM * CDIM,
            Wsc + i * NELEM * CDIM,
            Wread + i * CDIM,
            batch, out, i == 1 ? 1 : 0);
    }
}

// round 8
// speedup vs baseline: 1.2326x; 1.2326x over previous
#include <cuda_runtime.h>
#include <math.h>

#define N_NODES 8192
#define N_EDGES 65536
#define CDIM 64
#define NB 8
#define NELEM 10
#define NGRAPH 8

// Scratch (device globals; no allocation allowed)
__device__ float g_s[N_NODES * CDIM];
__device__ float g_m[N_NODES * CDIM];
__device__ float g_energy[N_NODES];
__device__ float g_ef[N_EDGES * NB];
__device__ int   g_elem[N_NODES];

// ---------------- packed f32x2 helpers (Blackwell FFMA2) -------------------
__device__ __forceinline__ unsigned long long pack2(float x, float y) {
    unsigned long long r;
    asm("mov.b64 %0, {%1, %2};" : "=l"(r) : "f"(x), "f"(y));
    return r;
}
__device__ __forceinline__ unsigned long long ffma2(unsigned long long a,
                                                    unsigned long long b,
                                                    unsigned long long c) {
    unsigned long long d;
    asm("fma.rn.f32x2 %0, %1, %2, %3;" : "=l"(d) : "l"(a), "l"(b), "l"(c));
    return d;
}
__device__ __forceinline__ float2 unpack2(unsigned long long v) {
    float x, y;
    asm("mov.b64 {%0, %1}, %2;" : "=f"(x), "=f"(y) : "l"(v));
    return make_float2(x, y);
}
__device__ __forceinline__ float silu(float x) {
    return __fdividef(x, 1.0f + __expf(-x));
}
// vectorized global reduction (sm_90+): one instr reduces 16B
__device__ __forceinline__ void red_add_v4(float* p, float a, float b,
                                           float c, float d) {
    asm volatile("red.global.add.v4.f32 [%0], {%1, %2, %3, %4};"
                 :: "l"(p), "f"(a), "f"(b), "f"(c), "f"(d) : "memory");
}

// ---------------------------------------------------------------------------
__global__ void init_kernel(const float* __restrict__ node_attrs,
                            const float* __restrict__ atomic_energies,
                            const float* __restrict__ W_embed,
                            float* __restrict__ d_out) {
    int n = blockIdx.x * blockDim.x + threadIdx.x;
    if (n >= N_NODES) return;
    if (n < NGRAPH) d_out[n] = 0.0f;

    const float* row = node_attrs + n * NELEM;
    int el = 0;
#pragma unroll
    for (int k = 0; k < NELEM; k++)
        if (row[k] > 0.5f) el = k;
    g_elem[n] = el;
    g_energy[n] = atomic_energies[el];

    const float4* we = (const float4*)(W_embed + el * CDIM);
    float4* srow = (float4*)(g_s + n * CDIM);
    float4* mrow = (float4*)(g_m + n * CDIM);
#pragma unroll
    for (int q = 0; q < CDIM / 4; q++) {
        srow[q] = we[q];
        mrow[q] = make_float4(0.f, 0.f, 0.f, 0.f);
    }
}

// ---------------------------------------------------------------------------
// edge features for one edge (bessel * poly cutoff); sh[:,0]==1
// ---------------------------------------------------------------------------
__device__ __forceinline__ void compute_ef(const float* __restrict__ positions,
                                           int snd, int rcv, float* ef) {
    float dx = positions[rcv * 3 + 0] - positions[snd * 3 + 0];
    float dy = positions[rcv * 3 + 1] - positions[snd * 3 + 1];
    float dz = positions[rcv * 3 + 2] - positions[snd * 3 + 2];
    float r = sqrtf(dx * dx + dy * dy + dz * dz);
    float rs = fmaxf(r, 1e-9f);
    float t = r * 0.2f;
    if (t < 1.0f) {
        float t2 = t * t;
        float t5 = t2 * t2 * t;
        float env = 1.0f - 21.0f * t5 + 35.0f * t5 * t - 15.0f * t5 * t2;
        float scale = 0.6324555320336759f * env / rs;
        float x = 0.62831853071795864769f * rs;
        float s1, c1;
        __sincosf(x, &s1, &c1);
        float twoc = 2.0f * c1;
        float sm1 = 0.0f, sn = s1;
#pragma unroll
        for (int k = 0; k < NB; k++) {
            ef[k] = sn * scale;
            float nxt = twoc * sn - sm1;
            sm1 = sn; sn = nxt;
        }
    } else {
#pragma unroll
        for (int k = 0; k < NB; k++) ef[k] = 0.0f;
    }
}

// ---------------------------------------------------------------------------
// edge MLP: block = 256 threads = 8 warps; warp w owns output slice
// [w*8, w*8+8); thread (warp, lane g) processes 4 edges (block: 128 edges).
// One 16KB smem buffer holds W2 during layers 1-2, reloaded with W3 (l=0
// slice) before layer 3. Scatter uses red.global.add.v4.f32 (4x fewer L1
// wavefronts than scalar atomics).
// ---------------------------------------------------------------------------
#define EPB 128

__global__ __launch_bounds__(256, 4) void edge_mlp_kernel(
    const float* __restrict__ w1, const float* __restrict__ b1,
    const float* __restrict__ w2, const float* __restrict__ b2,
    const float* __restrict__ w3, const int* __restrict__ edge_index,
    const float* __restrict__ positions, int first) {
    extern __shared__ float smp[];
    float* swb = smp;              // 4096 floats: W2, later W3
    float* act = smp + 4096;       // 8192 (transposed: [c][edge])
    float* sw1 = smp + 12288;      // 512
    float* sb1 = smp + 12800;      // 64
    float* sb2 = smp + 12864;      // 64

    int tid = threadIdx.x;
    for (int k = tid; k < 1024; k += 256)
        ((float4*)swb)[k] = ((const float4*)w2)[k];
    for (int k = tid; k < 128; k += 256)
        ((float4*)sw1)[k] = ((const float4*)w1)[k];
    if (tid < 64) { sb1[tid] = b1[tid]; sb2[tid] = b2[tid]; }

    int slice = tid >> 5;          // warp id = output slice
    int g = tid & 31;              // lane = edge group
    int s8 = slice * 8;
    int ebase = blockIdx.x * EPB + g * 4;

    // ---- edge features for 4 edges ----
    float ef[4][8];
    if (first) {
        int4 snd4 = *(const int4*)(edge_index + ebase);
        int4 rcv4 = *(const int4*)(edge_index + N_EDGES + ebase);
        const int* snds = &snd4.x;
        const int* rcvs = &rcv4.x;
#pragma unroll
        for (int e = 0; e < 4; e++) {
            compute_ef(positions, snds[e], rcvs[e], ef[e]);
            float4* out = (float4*)(g_ef + (ebase + e) * NB);
            out[0] = make_float4(ef[e][0], ef[e][1], ef[e][2], ef[e][3]);
            out[1] = make_float4(ef[e][4], ef[e][5], ef[e][6], ef[e][7]);
        }
    } else {
#pragma unroll
        for (int e = 0; e < 4; e++) {
            const float4* v = (const float4*)(g_ef + (ebase + e) * NB);
            float4 v0 = v[0], v1 = v[1];
            ef[e][0] = v0.x; ef[e][1] = v0.y; ef[e][2] = v0.z; ef[e][3] = v0.w;
            ef[e][4] = v1.x; ef[e][5] = v1.y; ef[e][6] = v1.z; ef[e][7] = v1.w;
        }
    }
    __syncthreads();

    // ---- layer 1: 8 -> 64 ----
    float a[4][8];
#pragma unroll
    for (int e = 0; e < 4; e++)
#pragma unroll
        for (int k = 0; k < 8; k++) a[e][k] = sb1[s8 + k];
#pragma unroll
    for (int c = 0; c < NB; c++) {
        float4 wa = *(const float4*)(sw1 + c * CDIM + s8);
        float4 wb = *(const float4*)(sw1 + c * CDIM + s8 + 4);
#pragma unroll
        for (int e = 0; e < 4; e++) {
            float x = ef[e][c];
            a[e][0] += x * wa.x; a[e][1] += x * wa.y;
            a[e][2] += x * wa.z; a[e][3] += x * wa.w;
            a[e][4] += x * wb.x; a[e][5] += x * wb.y;
            a[e][6] += x * wb.z; a[e][7] += x * wb.w;
        }
    }
#pragma unroll
    for (int k = 0; k < 8; k++) {
        float4 t = make_float4(silu(a[0][k]), silu(a[1][k]),
                               silu(a[2][k]), silu(a[3][k]));
        *(float4*)(act + (s8 + k) * EPB + g * 4) = t;
    }
    __syncthreads();

    // ---- layer 2: 64 -> 64 ----
    unsigned long long acc[4][4];
#pragma unroll
    for (int i = 0; i < 4; i++) {
        unsigned long long bi = pack2(sb2[s8 + 2 * i], sb2[s8 + 2 * i + 1]);
#pragma unroll
        for (int e = 0; e < 4; e++) acc[e][i] = bi;
    }
#pragma unroll 16
    for (int c = 0; c < CDIM; c++) {
        float4 av = *(const float4*)(act + c * EPB + g * 4);
        ulonglong2 wA = *(const ulonglong2*)(swb + c * CDIM + s8);
        ulonglong2 wB = *(const ulonglong2*)(swb + c * CDIM + s8 + 4);
        unsigned long long a0 = pack2(av.x, av.x);
        unsigned long long a1 = pack2(av.y, av.y);
        unsigned long long a2 = pack2(av.z, av.z);
        unsigned long long a3 = pack2(av.w, av.w);
        acc[0][0] = ffma2(a0, wA.x, acc[0][0]);
        acc[0][1] = ffma2(a0, wA.y, acc[0][1]);
        acc[0][2] = ffma2(a0, wB.x, acc[0][2]);
        acc[0][3] = ffma2(a0, wB.y, acc[0][3]);
        acc[1][0] = ffma2(a1, wA.x, acc[1][0]);
        acc[1][1] = ffma2(a1, wA.y, acc[1][1]);
        acc[1][2] = ffma2(a1, wB.x, acc[1][2]);
        acc[1][3] = ffma2(a1, wB.y, acc[1][3]);
        acc[2][0] = ffma2(a2, wA.x, acc[2][0]);
        acc[2][1] = ffma2(a2, wA.y, acc[2][1]);
        acc[2][2] = ffma2(a2, wB.x, acc[2][2]);
        acc[2][3] = ffma2(a2, wB.y, acc[2][3]);
        acc[3][0] = ffma2(a3, wA.x, acc[3][0]);
        acc[3][1] = ffma2(a3, wA.y, acc[3][1]);
        acc[3][2] = ffma2(a3, wB.x, acc[3][2]);
        acc[3][3] = ffma2(a3, wB.y, acc[3][3]);
    }
    __syncthreads();           // all reads of act AND swb(W2) done

    // reload swb with W3 (l=0 slice) while writing silu(act)
    for (int k = tid; k < 1024; k += 256) {
        int c = k >> 4, jq = k & 15;
        ((float4*)swb)[k] = ((const float4*)w3)[c * 64 + jq];
    }
#pragma unroll
    for (int i = 0; i < 4; i++) {
        float2 p0 = unpack2(acc[0][i]);
        float2 p1 = unpack2(acc[1][i]);
        float2 p2 = unpack2(acc[2][i]);
        float2 p3 = unpack2(acc[3][i]);
        float4 lo = make_float4(silu(p0.x), silu(p1.x), silu(p2.x), silu(p3.x));
        float4 hi = make_float4(silu(p0.y), silu(p1.y), silu(p2.y), silu(p3.y));
        *(float4*)(act + (s8 + 2 * i) * EPB + g * 4) = lo;
        *(float4*)(act + (s8 + 2 * i + 1) * EPB + g * 4) = hi;
    }
    __syncthreads();

    // ---- layer 3: 64 -> 64 (no bias/act) ----
#pragma unroll
    for (int e = 0; e < 4; e++)
#pragma unroll
        for (int i = 0; i < 4; i++) acc[e][i] = 0ull;
#pragma unroll 16
    for (int c = 0; c < CDIM; c++) {
        float4 av = *(const float4*)(act + c * EPB + g * 4);
        ulonglong2 wA = *(const ulonglong2*)(swb + c * CDIM + s8);
        ulonglong2 wB = *(const ulonglong2*)(swb + c * CDIM + s8 + 4);
        unsigned long long a0 = pack2(av.x, av.x);
        unsigned long long a1 = pack2(av.y, av.y);
        unsigned long long a2 = pack2(av.z, av.z);
        unsigned long long a3 = pack2(av.w, av.w);
        acc[0][0] = ffma2(a0, wA.x, acc[0][0]);
        acc[0][1] = ffma2(a0, wA.y, acc[0][1]);
        acc[0][2] = ffma2(a0, wB.x, acc[0][2]);
        acc[0][3] = ffma2(a0, wB.y, acc[0][3]);
        acc[1][0] = ffma2(a1, wA.x, acc[1][0]);
        acc[1][1] = ffma2(a1, wA.y, acc[1][1]);
        acc[1][2] = ffma2(a1, wB.x, acc[1][2]);
        acc[1][3] = ffma2(a1, wB.y, acc[1][3]);
        acc[2][0] = ffma2(a2, wA.x, acc[2][0]);
        acc[2][1] = ffma2(a2, wA.y, acc[2][1]);
        acc[2][2] = ffma2(a2, wB.x, acc[2][2]);
        acc[2][3] = ffma2(a2, wB.y, acc[2][3]);
        acc[3][0] = ffma2(a3, wA.x, acc[3][0]);
        acc[3][1] = ffma2(a3, wA.y, acc[3][1]);
        acc[3][2] = ffma2(a3, wB.x, acc[3][2]);
        acc[3][3] = ffma2(a3, wB.y, acc[3][3]);
    }

    // ---- message: msg = R0 * s[snd]; vector-reduce into m[rcv] ----
    int4 snd4 = *(const int4*)(edge_index + ebase);
    int4 rcv4 = *(const int4*)(edge_index + N_EDGES + ebase);
    const int* snds = &snd4.x;
    const int* rcvs = &rcv4.x;
#pragma unroll
    for (int e = 0; e < 4; e++) {
        float o[8];
#pragma unroll
        for (int i = 0; i < 4; i++) {
            float2 p = unpack2(acc[e][i]);
            o[2 * i] = p.x; o[2 * i + 1] = p.y;
        }
        int snd = snds[e], rcv = rcvs[e];
        const float4* srow = (const float4*)(g_s + snd * CDIM + s8);
        float4 sv0 = srow[0], sv1 = srow[1];
        float* mrow = g_m + rcv * CDIM + s8;
        red_add_v4(mrow, o[0] * sv0.x, o[1] * sv0.y,
                         o[2] * sv0.z, o[3] * sv0.w);
        red_add_v4(mrow + 4, o[4] * sv1.x, o[5] * sv1.y,
                             o[6] * sv1.z, o[7] * sv1.w);
    }
}

// ---------------------------------------------------------------------------
// node update: warp-per-node pair; 32 nodes/block.
// ---------------------------------------------------------------------------
#define NPB 32

__global__ __launch_bounds__(256) void node_kernel(
    const float* __restrict__ Wlin0,
    const float* __restrict__ Wprod,
    const float* __restrict__ Wsc,
    const float* __restrict__ Wread,
    const int* __restrict__ batch,
    float* __restrict__ d_out, int last) {
    __shared__ float swl[CDIM * CDIM];
    __shared__ float m_sm[NPB * CDIM];
    __shared__ float bins[NGRAPH];

    int tid = threadIdx.x;
    for (int k = tid; k < 1024; k += 256)
        ((float4*)swl)[k] = ((const float4*)Wlin0)[k];

    float4* gm = (float4*)(g_m + blockIdx.x * NPB * CDIM);
#pragma unroll
    for (int q = 0; q < 2; q++) {
        int idx = q * 256 + tid;
        float4 v = gm[idx];
        gm[idx] = make_float4(0.f, 0.f, 0.f, 0.f);
        ((float4*)m_sm)[idx] = make_float4(v.x * 0.125f, v.y * 0.125f,
                                           v.z * 0.125f, v.w * 0.125f);
    }
    if (tid < NGRAPH) bins[tid] = 0.0f;
    __syncthreads();

    int w = tid >> 5, g = tid & 31;
    int g2 = g * 2;

#pragma unroll
    for (int pair = 0; pair < 2; pair++) {
        int nl0 = w * 4 + pair * 2;
        const float* m0 = m_sm + nl0 * CDIM;
        const float* m1 = m0 + CDIM;
        unsigned long long acc0 = 0ull, acc1 = 0ull;
#pragma unroll 16
        for (int c = 0; c < CDIM; c++) {
            unsigned long long wv =
                *(const unsigned long long*)(swl + c * CDIM + g2);
            float av = m0[c], bv = m1[c];
            acc0 = ffma2(pack2(av, av), wv, acc0);
            acc1 = ffma2(pack2(bv, bv), wv, acc1);
        }
#pragma unroll
        for (int e = 0; e < 2; e++) {
            int node = blockIdx.x * NPB + nl0 + e;
            float2 f = unpack2(e ? acc1 : acc0);
            int el = g_elem[node];
            float2 w0 = *(const float2*)(Wprod + (0 * NELEM + el) * CDIM + g2);
            float2 w1 = *(const float2*)(Wprod + (1 * NELEM + el) * CDIM + g2);
            float2 w2 = *(const float2*)(Wprod + (2 * NELEM + el) * CDIM + g2);
            float2 sc = *(const float2*)(Wsc + el * CDIM + g2);
            float2 wr = *(const float2*)(Wread + g2);
            float2 sp = *(const float2*)(g_s + node * CDIM + g2);
            float hx = f.x * (w0.x + w1.x * f.x + w2.x * f.x * f.x) + sc.x * sp.x;
            float hy = f.y * (w0.y + w1.y * f.y + w2.y * f.y * f.y) + sc.y * sp.y;
            *(float2*)(g_s + node * CDIM + g2) = make_float2(hx, hy);
            float en = hx * wr.x + hy * wr.y;
#pragma unroll
            for (int off = 16; off > 0; off >>= 1)
                en += __shfl_down_sync(0xffffffffu, en, off);
            if (g == 0) {
                if (!last) g_energy[node] += en;
                else atomicAdd(&bins[batch[node]], g_energy[node] + en);
            }
        }
    }
    if (last) {
        __syncthreads();
        if (tid < NGRAPH) atomicAdd(d_out + tid, bins[tid]);
    }
}

// ---------------------------------------------------------------------------
extern "C" void kernel_launch(void* const* d_in, const int* in_sizes, int n_in,
                              void* d_out, int out_size) {
    const float* positions       = (const float*)d_in[0];
    const float* node_attrs      = (const float*)d_in[1];
    const int*   edge_index      = (const int*)d_in[2];
    const int*   batch           = (const int*)d_in[3];
    const float* atomic_energies = (const float*)d_in[4];
    const float* W_embed         = (const float*)d_in[5];
    const float* rw1             = (const float*)d_in[6];
    const float* rb1             = (const float*)d_in[7];
    const float* rw2             = (const float*)d_in[8];
    const float* rb2             = (const float*)d_in[9];
    const float* rw3             = (const float*)d_in[10];
    const float* Wlin            = (const float*)d_in[11];
    const float* Wprod           = (const float*)d_in[12];
    const float* Wsc             = (const float*)d_in[13];
    const float* Wread           = (const float*)d_in[14];
    float* out = (float*)d_out;

    const int EDGE_SMEM = 12928 * 4;   // 51712 B dynamic
    cudaFuncSetAttribute(edge_mlp_kernel,
                         cudaFuncAttributeMaxDynamicSharedMemorySize, EDGE_SMEM);

    init_kernel<<<N_NODES / 128, 128>>>(node_attrs, atomic_energies, W_embed, out);
    for (int i = 0; i < 2; i++) {
        edge_mlp_kernel<<<N_EDGES / EPB, 256, EDGE_SMEM>>>(
            rw1 + i * NB * CDIM, rb1 + i * CDIM,
            rw2 + i * CDIM * CDIM, rb2 + i * CDIM,
            rw3 + i * CDIM * 4 * CDIM, edge_index, positions, i == 0 ? 1 : 0);
        node_kernel<<<N_NODES / NPB, 256>>>(
            Wlin + i * 4 * CDIM * CDIM,
            Wprod + i * 3 * NELEM * CDIM,
            Wsc + i * NELEM * CDIM,
            Wread + i * CDIM,
            batch, out, i == 1 ? 1 : 0);
    }
}

// round 9
// speedup vs baseline: 2.0240x; 1.6420x over previous
#include <cuda_runtime.h>
#include <math.h>

#define N_NODES 8192
#define N_EDGES 65536
#define CDIM 64
#define NB 8
#define NELEM 10
#define NGRAPH 8
#define TBL_N 8192               // interpolation intervals over [0, R_MAX]
#define TBL_PTS (TBL_N + 1)

// Scratch (device globals; no allocation allowed)
__device__ float g_s[N_NODES * CDIM];
__device__ float g_m[N_NODES * CDIM];
__device__ float g_energy[N_NODES];
__device__ float g_r[N_EDGES];
__device__ int   g_elem[N_NODES];
__device__ float g_tbl[2 * TBL_PTS * CDIM];   // R0(r) tables, 4.2 MB

// ---------------- packed f32x2 helpers (Blackwell FFMA2) -------------------
__device__ __forceinline__ unsigned long long pack2(float x, float y) {
    unsigned long long r;
    asm("mov.b64 %0, {%1, %2};" : "=l"(r) : "f"(x), "f"(y));
    return r;
}
__device__ __forceinline__ unsigned long long ffma2(unsigned long long a,
                                                    unsigned long long b,
                                                    unsigned long long c) {
    unsigned long long d;
    asm("fma.rn.f32x2 %0, %1, %2, %3;" : "=l"(d) : "l"(a), "l"(b), "l"(c));
    return d;
}
__device__ __forceinline__ float2 unpack2(unsigned long long v) {
    float x, y;
    asm("mov.b64 {%0, %1}, %2;" : "=f"(x), "=f"(y) : "l"(v));
    return make_float2(x, y);
}
__device__ __forceinline__ float silu(float x) {
    return __fdividef(x, 1.0f + __expf(-x));
}
__device__ __forceinline__ void red_add_v4(float* p, float a, float b,
                                           float c, float d) {
    asm volatile("red.global.add.v4.f32 [%0], {%1, %2, %3, %4};"
                 :: "l"(p), "f"(a), "f"(b), "f"(c), "f"(d) : "memory");
}

// ---------------------------------------------------------------------------
__global__ void init_kernel(const float* __restrict__ node_attrs,
                            const float* __restrict__ atomic_energies,
                            const float* __restrict__ W_embed,
                            float* __restrict__ d_out) {
    int n = blockIdx.x * blockDim.x + threadIdx.x;
    if (n >= N_NODES) return;
    if (n < NGRAPH) d_out[n] = 0.0f;

    const float* row = node_attrs + n * NELEM;
    int el = 0;
#pragma unroll
    for (int k = 0; k < NELEM; k++)
        if (row[k] > 0.5f) el = k;
    g_elem[n] = el;
    g_energy[n] = atomic_energies[el];

    const float4* we = (const float4*)(W_embed + el * CDIM);
    float4* srow = (float4*)(g_s + n * CDIM);
    float4* mrow = (float4*)(g_m + n * CDIM);
#pragma unroll
    for (int q = 0; q < CDIM / 4; q++) {
        srow[q] = we[q];
        mrow[q] = make_float4(0.f, 0.f, 0.f, 0.f);
    }
}

// ---------------------------------------------------------------------------
// radial features from scalar r (bessel * poly cutoff)
// ---------------------------------------------------------------------------
__device__ __forceinline__ void compute_ef_r(float r, float* ef) {
    float rs = fmaxf(r, 1e-9f);
    float t = r * 0.2f;
    if (t < 1.0f) {
        float t2 = t * t;
        float t5 = t2 * t2 * t;
        float env = 1.0f - 21.0f * t5 + 35.0f * t5 * t - 15.0f * t5 * t2;
        float scale = 0.6324555320336759f * env / rs;
        float x = 0.62831853071795864769f * rs;
        float s1, c1;
        __sincosf(x, &s1, &c1);
        float twoc = 2.0f * c1;
        float sm1 = 0.0f, sn = s1;
#pragma unroll
        for (int k = 0; k < NB; k++) {
            ef[k] = sn * scale;
            float nxt = twoc * sn - sm1;
            sm1 = sn; sn = nxt;
        }
    } else {
#pragma unroll
        for (int k = 0; k < NB; k++) ef[k] = 0.0f;
    }
}

// ---------------------------------------------------------------------------
// table build: R0(r) = l=0 radial-MLP output, tabulated on TBL_PTS points
// per interaction. One thread per point; weights staged in smem (broadcast).
// ---------------------------------------------------------------------------
#define BPT 65   // ceil(TBL_PTS / 128)

__global__ __launch_bounds__(128) void table_kernel(
    const float* __restrict__ rw1, const float* __restrict__ rb1,
    const float* __restrict__ rw2, const float* __restrict__ rb2,
    const float* __restrict__ rw3) {
    __shared__ float sw1[NB * CDIM];
    __shared__ float sb1[CDIM];
    __shared__ float sw2[CDIM * CDIM];
    __shared__ float sb2[CDIM];
    __shared__ float sw3[CDIM * CDIM];

    int i = blockIdx.x / BPT;
    int pt = (blockIdx.x % BPT) * 128 + threadIdx.x;
    const float* w1 = rw1 + i * NB * CDIM;
    const float* b1 = rb1 + i * CDIM;
    const float* w2 = rw2 + i * CDIM * CDIM;
    const float* b2 = rb2 + i * CDIM;
    const float* w3 = rw3 + i * CDIM * 4 * CDIM;

    int tid = threadIdx.x;
    for (int k = tid; k < NB * CDIM / 4; k += 128)
        ((float4*)sw1)[k] = ((const float4*)w1)[k];
    for (int k = tid; k < CDIM * CDIM / 4; k += 128)
        ((float4*)sw2)[k] = ((const float4*)w2)[k];
    for (int k = tid; k < CDIM * CDIM / 4; k += 128) {
        int c = k >> 4, jq = k & 15;          // l=0 slice of (64,256)
        ((float4*)sw3)[k] = ((const float4*)w3)[c * 64 + jq];
    }
    if (tid < CDIM) { sb1[tid] = b1[tid]; sb2[tid] = b2[tid]; }
    __syncthreads();
    if (pt >= TBL_PTS) return;

    float r = (float)pt * (5.0f / (float)TBL_N);
    float ef[NB];
    compute_ef_r(r, ef);

    float a[CDIM], b[CDIM];
    // layer 1: 8 -> 64
#pragma unroll
    for (int j = 0; j < CDIM; j++) a[j] = sb1[j];
#pragma unroll
    for (int c = 0; c < NB; c++) {
        float x = ef[c];
        const float4* wr = (const float4*)(sw1 + c * CDIM);
#pragma unroll
        for (int j4 = 0; j4 < CDIM / 4; j4++) {
            float4 w = wr[j4];
            a[4 * j4 + 0] += x * w.x;
            a[4 * j4 + 1] += x * w.y;
            a[4 * j4 + 2] += x * w.z;
            a[4 * j4 + 3] += x * w.w;
        }
    }
#pragma unroll
    for (int j = 0; j < CDIM; j++) a[j] = silu(a[j]);

    // layer 2: 64 -> 64
#pragma unroll
    for (int j = 0; j < CDIM; j++) b[j] = sb2[j];
#pragma unroll
    for (int c = 0; c < CDIM; c++) {
        float x = a[c];
        const float4* wr = (const float4*)(sw2 + c * CDIM);
#pragma unroll
        for (int j4 = 0; j4 < CDIM / 4; j4++) {
            float4 w = wr[j4];
            b[4 * j4 + 0] += x * w.x;
            b[4 * j4 + 1] += x * w.y;
            b[4 * j4 + 2] += x * w.z;
            b[4 * j4 + 3] += x * w.w;
        }
    }
#pragma unroll
    for (int j = 0; j < CDIM; j++) b[j] = silu(b[j]);

    // layer 3: 64 -> 64 (no bias/act) into a
#pragma unroll
    for (int j = 0; j < CDIM; j++) a[j] = 0.0f;
#pragma unroll
    for (int c = 0; c < CDIM; c++) {
        float x = b[c];
        const float4* wr = (const float4*)(sw3 + c * CDIM);
#pragma unroll
        for (int j4 = 0; j4 < CDIM / 4; j4++) {
            float4 w = wr[j4];
            a[4 * j4 + 0] += x * w.x;
            a[4 * j4 + 1] += x * w.y;
            a[4 * j4 + 2] += x * w.z;
            a[4 * j4 + 3] += x * w.w;
        }
    }

    float* dst = g_tbl + (i * TBL_PTS + pt) * CDIM;
#pragma unroll
    for (int j4 = 0; j4 < CDIM / 4; j4++)
        *(float4*)(dst + 4 * j4) = make_float4(a[4 * j4 + 0], a[4 * j4 + 1],
                                               a[4 * j4 + 2], a[4 * j4 + 3]);
}

// ---------------------------------------------------------------------------
// edge pass: r -> table interp -> msg = R0(r) * s[snd] -> red.v4 into m[rcv].
// 8 threads per edge (8-channel slices), 32 edges / 256-thr block.
// ---------------------------------------------------------------------------
__global__ __launch_bounds__(256) void edge_scatter_kernel(
    const int* __restrict__ edge_index,
    const float* __restrict__ positions,
    int interaction) {
    int tid = threadIdx.x;
    int e = blockIdx.x * 32 + (tid >> 3);
    int s8 = (tid & 7) * 8;
    int snd = edge_index[e];
    int rcv = edge_index[N_EDGES + e];

    float r;
    if (interaction == 0) {
        float dx = positions[rcv * 3 + 0] - positions[snd * 3 + 0];
        float dy = positions[rcv * 3 + 1] - positions[snd * 3 + 1];
        float dz = positions[rcv * 3 + 2] - positions[snd * 3 + 2];
        r = sqrtf(dx * dx + dy * dy + dz * dz);
        if ((tid & 7) == 0) g_r[e] = r;
    } else {
        r = g_r[e];
    }

    float u = r * ((float)TBL_N / 5.0f);
    int i0; float fr;
    if (u >= (float)TBL_N) { i0 = TBL_N - 1; fr = 1.0f; }
    else { i0 = (int)u; fr = u - (float)i0; }

    const float* tb = g_tbl + (interaction * TBL_PTS + i0) * CDIM + s8;
    float4 a0 = *(const float4*)(tb);
    float4 a1 = *(const float4*)(tb + 4);
    float4 b0 = *(const float4*)(tb + CDIM);
    float4 b1 = *(const float4*)(tb + CDIM + 4);

    const float4* srow = (const float4*)(g_s + snd * CDIM + s8);
    float4 s0 = srow[0], s1 = srow[1];
    float* mrow = g_m + rcv * CDIM + s8;
    red_add_v4(mrow,
               (a0.x + fr * (b0.x - a0.x)) * s0.x,
               (a0.y + fr * (b0.y - a0.y)) * s0.y,
               (a0.z + fr * (b0.z - a0.z)) * s0.z,
               (a0.w + fr * (b0.w - a0.w)) * s0.w);
    red_add_v4(mrow + 4,
               (a1.x + fr * (b1.x - a1.x)) * s1.x,
               (a1.y + fr * (b1.y - a1.y)) * s1.y,
               (a1.z + fr * (b1.z - a1.z)) * s1.z,
               (a1.w + fr * (b1.w - a1.w)) * s1.w);
}

// ---------------------------------------------------------------------------
// node update: warp-per-node pair; 32 nodes/block.
// ---------------------------------------------------------------------------
#define NPB 32

__global__ __launch_bounds__(256) void node_kernel(
    const float* __restrict__ Wlin0,
    const float* __restrict__ Wprod,
    const float* __restrict__ Wsc,
    const float* __restrict__ Wread,
    const int* __restrict__ batch,
    float* __restrict__ d_out, int last) {
    __shared__ float swl[CDIM * CDIM];
    __shared__ float m_sm[NPB * CDIM];
    __shared__ float bins[NGRAPH];

    int tid = threadIdx.x;
    for (int k = tid; k < 1024; k += 256)
        ((float4*)swl)[k] = ((const float4*)Wlin0)[k];

    float4* gm = (float4*)(g_m + blockIdx.x * NPB * CDIM);
#pragma unroll
    for (int q = 0; q < 2; q++) {
        int idx = q * 256 + tid;
        float4 v = gm[idx];
        gm[idx] = make_float4(0.f, 0.f, 0.f, 0.f);
        ((float4*)m_sm)[idx] = make_float4(v.x * 0.125f, v.y * 0.125f,
                                           v.z * 0.125f, v.w * 0.125f);
    }
    if (tid < NGRAPH) bins[tid] = 0.0f;
    __syncthreads();

    int w = tid >> 5, g = tid & 31;
    int g2 = g * 2;

#pragma unroll
    for (int pair = 0; pair < 2; pair++) {
        int nl0 = w * 4 + pair * 2;
        const float* m0 = m_sm + nl0 * CDIM;
        const float* m1 = m0 + CDIM;
        unsigned long long acc0 = 0ull, acc1 = 0ull;
#pragma unroll 16
        for (int c = 0; c < CDIM; c++) {
            unsigned long long wv =
                *(const unsigned long long*)(swl + c * CDIM + g2);
            float av = m0[c], bv = m1[c];
            acc0 = ffma2(pack2(av, av), wv, acc0);
            acc1 = ffma2(pack2(bv, bv), wv, acc1);
        }
#pragma unroll
        for (int e = 0; e < 2; e++) {
            int node = blockIdx.x * NPB + nl0 + e;
            float2 f = unpack2(e ? acc1 : acc0);
            int el = g_elem[node];
            float2 w0 = *(const float2*)(Wprod + (0 * NELEM + el) * CDIM + g2);
            float2 w1 = *(const float2*)(Wprod + (1 * NELEM + el) * CDIM + g2);
            float2 w2 = *(const float2*)(Wprod + (2 * NELEM + el) * CDIM + g2);
            float2 sc = *(const float2*)(Wsc + el * CDIM + g2);
            float2 wr = *(const float2*)(Wread + g2);
            float2 sp = *(const float2*)(g_s + node * CDIM + g2);
            float hx = f.x * (w0.x + w1.x * f.x + w2.x * f.x * f.x) + sc.x * sp.x;
            float hy = f.y * (w0.y + w1.y * f.y + w2.y * f.y * f.y) + sc.y * sp.y;
            *(float2*)(g_s + node * CDIM + g2) = make_float2(hx, hy);
            float en = hx * wr.x + hy * wr.y;
#pragma unroll
            for (int off = 16; off > 0; off >>= 1)
                en += __shfl_down_sync(0xffffffffu, en, off);
            if (g == 0) {
                if (!last) g_energy[node] += en;
                else atomicAdd(&bins[batch[node]], g_energy[node] + en);
            }
        }
    }
    if (last) {
        __syncthreads();
        if (tid < NGRAPH) atomicAdd(d_out + tid, bins[tid]);
    }
}

// ---------------------------------------------------------------------------
extern "C" void kernel_launch(void* const* d_in, const int* in_sizes, int n_in,
                              void* d_out, int out_size) {
    const float* positions       = (const float*)d_in[0];
    const float* node_attrs      = (const float*)d_in[1];
    const int*   edge_index      = (const int*)d_in[2];
    const int*   batch           = (const int*)d_in[3];
    const float* atomic_energies = (const float*)d_in[4];
    const float* W_embed         = (const float*)d_in[5];
    const float* rw1             = (const float*)d_in[6];
    const float* rb1             = (const float*)d_in[7];
    const float* rw2             = (const float*)d_in[8];
    const float* rb2             = (const float*)d_in[9];
    const float* rw3             = (const float*)d_in[10];
    const float* Wlin            = (const float*)d_in[11];
    const float* Wprod           = (const float*)d_in[12];
    const float* Wsc             = (const float*)d_in[13];
    const float* Wread           = (const float*)d_in[14];
    float* out = (float*)d_out;

    init_kernel<<<N_NODES / 128, 128>>>(node_attrs, atomic_energies, W_embed, out);
    table_kernel<<<2 * BPT, 128>>>(rw1, rb1, rw2, rb2, rw3);
    for (int i = 0; i < 2; i++) {
        edge_scatter_kernel<<<N_EDGES / 32, 256>>>(edge_index, positions, i);
        node_kernel<<<N_NODES / NPB, 256>>>(
            Wlin + i * 4 * CDIM * CDIM,
            Wprod + i * 3 * NELEM * CDIM,
            Wsc + i * NELEM * CDIM,
            Wread + i * CDIM,
            batch, out, i == 1 ? 1 : 0);
    }
}

// round 11
// speedup vs baseline: 2.1147x; 1.0448x over previous
#include <cuda_runtime.h>
#include <math.h>

#define N_NODES 8192
#define N_EDGES 65536
#define CDIM 64
#define NB 8
#define NELEM 10
#define NGRAPH 8
#define TBL_N 2048               // interpolation intervals over [0, R_MAX]
#define TBL_PTS (TBL_N + 1)
#define BPT 17                   // ceil(TBL_PTS / 128)

// Scratch (device globals; no allocation allowed)
__device__ float g_s[N_NODES * CDIM];
__device__ float g_m[N_NODES * CDIM];
__device__ float g_energy[N_NODES];
__device__ float g_r[N_EDGES];
__device__ int   g_elem[N_NODES];
__device__ float g_tbl[2 * TBL_PTS * CDIM];   // R0(r) tables, ~1 MB

// ---------------- packed f32x2 helpers (Blackwell FFMA2) -------------------
__device__ __forceinline__ unsigned long long pack2(float x, float y) {
    unsigned long long r;
    asm("mov.b64 %0, {%1, %2};" : "=l"(r) : "f"(x), "f"(y));
    return r;
}
__device__ __forceinline__ unsigned long long ffma2(unsigned long long a,
                                                    unsigned long long b,
                                                    unsigned long long c) {
    unsigned long long d;
    asm("fma.rn.f32x2 %0, %1, %2, %3;" : "=l"(d) : "l"(a), "l"(b), "l"(c));
    return d;
}
__device__ __forceinline__ float2 unpack2(unsigned long long v) {
    float x, y;
    asm("mov.b64 {%0, %1}, %2;" : "=f"(x), "=f"(y) : "l"(v));
    return make_float2(x, y);
}
__device__ __forceinline__ float silu(float x) {
    return __fdividef(x, 1.0f + __expf(-x));
}
__device__ __forceinline__ void red_add_v4(float* p, float a, float b,
                                           float c, float d) {
    asm volatile("red.global.add.v4.f32 [%0], {%1, %2, %3, %4};"
                 :: "l"(p), "f"(a), "f"(b), "f"(c), "f"(d) : "memory");
}

// ---------------------------------------------------------------------------
// radial features from scalar r (bessel * poly cutoff)
// ---------------------------------------------------------------------------
__device__ __forceinline__ void compute_ef_r(float r, float* ef) {
    float rs = fmaxf(r, 1e-9f);
    float t = r * 0.2f;
    if (t < 1.0f) {
        float t2 = t * t;
        float t5 = t2 * t2 * t;
        float env = 1.0f - 21.0f * t5 + 35.0f * t5 * t - 15.0f * t5 * t2;
        float scale = 0.6324555320336759f * env / rs;
        float x = 0.62831853071795864769f * rs;
        float s1, c1;
        __sincosf(x, &s1, &c1);
        float twoc = 2.0f * c1;
        float sm1 = 0.0f, sn = s1;
#pragma unroll
        for (int k = 0; k < NB; k++) {
            ef[k] = sn * scale;
            float nxt = twoc * sn - sm1;
            sm1 = sn; sn = nxt;
        }
    } else {
#pragma unroll
        for (int k = 0; k < NB; k++) ef[k] = 0.0f;
    }
}

// ---------------------------------------------------------------------------
// boot: blocks [0,64) do node init; blocks [64, 64+2*BPT) build R0 tables.
// ---------------------------------------------------------------------------
__global__ __launch_bounds__(128) void boot_kernel(
    const float* __restrict__ node_attrs,
    const float* __restrict__ atomic_energies,
    const float* __restrict__ W_embed,
    float* __restrict__ d_out,
    const float* __restrict__ rw1, const float* __restrict__ rb1,
    const float* __restrict__ rw2, const float* __restrict__ rb2,
    const float* __restrict__ rw3) {
    int tid = threadIdx.x;

    if (blockIdx.x < 64) {
        // ---------------- init part ----------------
        int n = blockIdx.x * 128 + tid;
        if (n < NGRAPH) d_out[n] = 0.0f;

        const float* row = node_attrs + n * NELEM;
        int el = 0;
#pragma unroll
        for (int k = 0; k < NELEM; k++)
            if (row[k] > 0.5f) el = k;
        g_elem[n] = el;
        g_energy[n] = atomic_energies[el];

        const float4* we = (const float4*)(W_embed + el * CDIM);
        float4* srow = (float4*)(g_s + n * CDIM);
        float4* mrow = (float4*)(g_m + n * CDIM);
#pragma unroll
        for (int q = 0; q < CDIM / 4; q++) {
            srow[q] = we[q];
            mrow[q] = make_float4(0.f, 0.f, 0.f, 0.f);
        }
        return;
    }

    // ---------------- table part ----------------
    __shared__ float sw1[NB * CDIM];
    __shared__ float sb1[CDIM];
    __shared__ float sw2[CDIM * CDIM];
    __shared__ float sb2[CDIM];
    __shared__ float sw3[CDIM * CDIM];

    int b = blockIdx.x - 64;
    int i = b / BPT;
    int pt = (b % BPT) * 128 + tid;
    const float* w1 = rw1 + i * NB * CDIM;
    const float* b1 = rb1 + i * CDIM;
    const float* w2 = rw2 + i * CDIM * CDIM;
    const float* b2 = rb2 + i * CDIM;
    const float* w3 = rw3 + i * CDIM * 4 * CDIM;

    for (int k = tid; k < NB * CDIM / 4; k += 128)
        ((float4*)sw1)[k] = ((const float4*)w1)[k];
    for (int k = tid; k < CDIM * CDIM / 4; k += 128)
        ((float4*)sw2)[k] = ((const float4*)w2)[k];
    for (int k = tid; k < CDIM * CDIM / 4; k += 128) {
        int c = k >> 4, jq = k & 15;          // l=0 slice of (64,256)
        ((float4*)sw3)[k] = ((const float4*)w3)[c * 64 + jq];
    }
    if (tid < CDIM) { sb1[tid] = b1[tid]; sb2[tid] = b2[tid]; }
    __syncthreads();
    if (pt >= TBL_PTS) return;

    float r = (float)pt * (5.0f / (float)TBL_N);
    float ef[NB];
    compute_ef_r(r, ef);

    float a[CDIM], bb[CDIM];
    // layer 1: 8 -> 64
#pragma unroll
    for (int j = 0; j < CDIM; j++) a[j] = sb1[j];
#pragma unroll
    for (int c = 0; c < NB; c++) {
        float x = ef[c];
        const float4* wr = (const float4*)(sw1 + c * CDIM);
#pragma unroll
        for (int j4 = 0; j4 < CDIM / 4; j4++) {
            float4 w = wr[j4];
            a[4 * j4 + 0] += x * w.x;
            a[4 * j4 + 1] += x * w.y;
            a[4 * j4 + 2] += x * w.z;
            a[4 * j4 + 3] += x * w.w;
        }
    }
#pragma unroll
    for (int j = 0; j < CDIM; j++) a[j] = silu(a[j]);

    // layer 2: 64 -> 64
#pragma unroll
    for (int j = 0; j < CDIM; j++) bb[j] = sb2[j];
#pragma unroll
    for (int c = 0; c < CDIM; c++) {
        float x = a[c];
        const float4* wr = (const float4*)(sw2 + c * CDIM);
#pragma unroll
        for (int j4 = 0; j4 < CDIM / 4; j4++) {
            float4 w = wr[j4];
            bb[4 * j4 + 0] += x * w.x;
            bb[4 * j4 + 1] += x * w.y;
            bb[4 * j4 + 2] += x * w.z;
            bb[4 * j4 + 3] += x * w.w;
        }
    }
#pragma unroll
    for (int j = 0; j < CDIM; j++) bb[j] = silu(bb[j]);

    // layer 3: 64 -> 64 (no bias/act) into a
#pragma unroll
    for (int j = 0; j < CDIM; j++) a[j] = 0.0f;
#pragma unroll
    for (int c = 0; c < CDIM; c++) {
        float x = bb[c];
        const float4* wr = (const float4*)(sw3 + c * CDIM);
#pragma unroll
        for (int j4 = 0; j4 < CDIM / 4; j4++) {
            float4 w = wr[j4];
            a[4 * j4 + 0] += x * w.x;
            a[4 * j4 + 1] += x * w.y;
            a[4 * j4 + 2] += x * w.z;
            a[4 * j4 + 3] += x * w.w;
        }
    }

    float* dst = g_tbl + (i * TBL_PTS + pt) * CDIM;
#pragma unroll
    for (int j4 = 0; j4 < CDIM / 4; j4++)
        *(float4*)(dst + 4 * j4) = make_float4(a[4 * j4 + 0], a[4 * j4 + 1],
                                               a[4 * j4 + 2], a[4 * j4 + 3]);
}

// ---------------------------------------------------------------------------
// edge pass: r -> table interp -> msg = R0(r) * s[snd] -> red.v4 into m[rcv].
// 8 threads per edge (8-channel slices), 32 edges / 256-thr block.
// ---------------------------------------------------------------------------
__global__ __launch_bounds__(256) void edge_scatter_kernel(
    const int* __restrict__ edge_index,
    const float* __restrict__ positions,
    int interaction) {
    int tid = threadIdx.x;
    int e = blockIdx.x * 32 + (tid >> 3);
    int s8 = (tid & 7) * 8;
    int snd = edge_index[e];
    int rcv = edge_index[N_EDGES + e];

    float r;
    if (interaction == 0) {
        float dx = positions[rcv * 3 + 0] - positions[snd * 3 + 0];
        float dy = positions[rcv * 3 + 1] - positions[snd * 3 + 1];
        float dz = positions[rcv * 3 + 2] - positions[snd * 3 + 2];
        r = sqrtf(dx * dx + dy * dy + dz * dz);
        if ((tid & 7) == 0) g_r[e] = r;
    } else {
        r = g_r[e];
    }

    float u = r * ((float)TBL_N / 5.0f);
    int i0; float fr;
    if (u >= (float)TBL_N) { i0 = TBL_N - 1; fr = 1.0f; }
    else { i0 = (int)u; fr = u - (float)i0; }

    const float* tb = g_tbl + (interaction * TBL_PTS + i0) * CDIM + s8;
    float4 a0 = *(const float4*)(tb);
    float4 a1 = *(const float4*)(tb + 4);
    float4 b0 = *(const float4*)(tb + CDIM);
    float4 b1 = *(const float4*)(tb + CDIM + 4);

    const float4* srow = (const float4*)(g_s + snd * CDIM + s8);
    float4 s0 = srow[0], s1 = srow[1];
    float* mrow = g_m + rcv * CDIM + s8;
    red_add_v4(mrow,
               (a0.x + fr * (b0.x - a0.x)) * s0.x,
               (a0.y + fr * (b0.y - a0.y)) * s0.y,
               (a0.z + fr * (b0.z - a0.z)) * s0.z,
               (a0.w + fr * (b0.w - a0.w)) * s0.w);
    red_add_v4(mrow + 4,
               (a1.x + fr * (b1.x - a1.x)) * s1.x,
               (a1.y + fr * (b1.y - a1.y)) * s1.y,
               (a1.z + fr * (b1.z - a1.z)) * s1.z,
               (a1.w + fr * (b1.w - a1.w)) * s1.w);
}

// ---------------------------------------------------------------------------
// node update: 64 nodes/block, 512 threads (16 warps x 4 nodes), grid 128
// => single wave, weight load amortized over 64 nodes.
// ---------------------------------------------------------------------------
#define NPB 64

__global__ __launch_bounds__(512) void node_kernel(
    const float* __restrict__ Wlin0,
    const float* __restrict__ Wprod,
    const float* __restrict__ Wsc,
    const float* __restrict__ Wread,
    const int* __restrict__ batch,
    float* __restrict__ d_out, int last) {
    __shared__ float swl[CDIM * CDIM];
    __shared__ float m_sm[NPB * CDIM];
    __shared__ float bins[NGRAPH];

    int tid = threadIdx.x;
    for (int k = tid; k < 1024; k += 512)
        ((float4*)swl)[k] = ((const float4*)Wlin0)[k];

    float4* gm = (float4*)(g_m + blockIdx.x * NPB * CDIM);
#pragma unroll
    for (int q = 0; q < 2; q++) {
        int idx = q * 512 + tid;
        float4 v = gm[idx];
        gm[idx] = make_float4(0.f, 0.f, 0.f, 0.f);
        ((float4*)m_sm)[idx] = make_float4(v.x * 0.125f, v.y * 0.125f,
                                           v.z * 0.125f, v.w * 0.125f);
    }
    if (tid < NGRAPH) bins[tid] = 0.0f;
    __syncthreads();

    int w = tid >> 5, g = tid & 31;   // 16 warps
    int g2 = g * 2;

#pragma unroll
    for (int pair = 0; pair < 2; pair++) {
        int nl0 = w * 4 + pair * 2;
        const float* m0 = m_sm + nl0 * CDIM;
        const float* m1 = m0 + CDIM;
        unsigned long long acc0 = 0ull, acc1 = 0ull;
#pragma unroll 16
        for (int c = 0; c < CDIM; c++) {
            unsigned long long wv =
                *(const unsigned long long*)(swl + c * CDIM + g2);
            float av = m0[c], bv = m1[c];
            acc0 = ffma2(pack2(av, av), wv, acc0);
            acc1 = ffma2(pack2(bv, bv), wv, acc1);
        }
#pragma unroll
        for (int e = 0; e < 2; e++) {
            int node = blockIdx.x * NPB + nl0 + e;
            float2 f = unpack2(e ? acc1 : acc0);
            int el = g_elem[node];
            float2 w0 = *(const float2*)(Wprod + (0 * NELEM + el) * CDIM + g2);
            float2 w1 = *(const float2*)(Wprod + (1 * NELEM + el) * CDIM + g2);
            float2 w2 = *(const float2*)(Wprod + (2 * NELEM + el) * CDIM + g2);
            float2 sc = *(const float2*)(Wsc + el * CDIM + g2);
            float2 wr = *(const float2*)(Wread + g2);
            float2 sp = *(const float2*)(g_s + node * CDIM + g2);
            float hx = f.x * (w0.x + w1.x * f.x + w2.x * f.x * f.x) + sc.x * sp.x;
            float hy = f.y * (w0.y + w1.y * f.y + w2.y * f.y * f.y) + sc.y * sp.y;
            *(float2*)(g_s + node * CDIM + g2) = make_float2(hx, hy);
            float en = hx * wr.x + hy * wr.y;
#pragma unroll
            for (int off = 16; off > 0; off >>= 1)
                en += __shfl_down_sync(0xffffffffu, en, off);
            if (g == 0) {
                if (!last) g_energy[node] += en;
                else atomicAdd(&bins[batch[node]], g_energy[node] + en);
            }
        }
    }
    if (last) {
        __syncthreads();
        if (tid < NGRAPH) atomicAdd(d_out + tid, bins[tid]);
    }
}

// ---------------------------------------------------------------------------
extern "C" void kernel_launch(void* const* d_in, const int* in_sizes, int n_in,
                              void* d_out, int out_size) {
    const float* positions       = (const float*)d_in[0];
    const float* node_attrs      = (const float*)d_in[1];
    const int*   edge_index      = (const int*)d_in[2];
    const int*   batch           = (const int*)d_in[3];
    const float* atomic_energies = (const float*)d_in[4];
    const float* W_embed         = (const float*)d_in[5];
    const float* rw1             = (const float*)d_in[6];
    const float* rb1             = (const float*)d_in[7];
    const float* rw2             = (const float*)d_in[8];
    const float* rb2             = (const float*)d_in[9];
    const float* rw3             = (const float*)d_in[10];
    const float* Wlin            = (const float*)d_in[11];
    const float* Wprod           = (const float*)d_in[12];
    const float* Wsc             = (const float*)d_in[13];
    const float* Wread           = (const float*)d_in[14];
    float* out = (float*)d_out;

    boot_kernel<<<64 + 2 * BPT, 128>>>(node_attrs, atomic_energies, W_embed,
                                       out, rw1, rb1, rw2, rb2, rw3);
    for (int i = 0; i < 2; i++) {
        edge_scatter_kernel<<<N_EDGES / 32, 256>>>(edge_index, positions, i);
        node_kernel<<<N_NODES / NPB, 512>>>(
            Wlin + i * 4 * CDIM * CDIM,
            Wprod + i * 3 * NELEM * CDIM,
            Wsc + i * NELEM * CDIM,
            Wread + i * CDIM,
            batch, out, i == 1 ? 1 : 0);
    }
}

// round 13
// speedup vs baseline: 2.5018x; 1.1830x over previous
#include <cuda_runtime.h>
#include <math.h>

#define N_NODES 8192
#define N_EDGES 65536
#define CDIM 64
#define NB 8
#define NELEM 10
#define NGRAPH 8
#define TBL_N 2048
#define TBL_PTS (TBL_N + 1)
#define GRID 128
#define THREADS 512
#define NPB 64                      // nodes per block (8192/128)
#define PPB 33                      // table points per block per interaction
#define ACT_STRIDE 68               // padded act row (bank-shift)

// Scratch (device globals; no allocation allowed)
__device__ float g_s[N_NODES * CDIM];
__device__ float g_m[N_NODES * CDIM];
__device__ float g_energy[N_NODES];
__device__ float g_r[N_EDGES];
__device__ int   g_elem[N_NODES];
__device__ float g_tbl[2 * TBL_PTS * CDIM];
__device__ unsigned g_bar[4];
__device__ unsigned g_ack;

// ---------------- packed f32x2 helpers -------------------------------------
__device__ __forceinline__ unsigned long long pack2(float x, float y) {
    unsigned long long r;
    asm("mov.b64 %0, {%1, %2};" : "=l"(r) : "f"(x), "f"(y));
    return r;
}
__device__ __forceinline__ unsigned long long ffma2(unsigned long long a,
                                                    unsigned long long b,
                                                    unsigned long long c) {
    unsigned long long d;
    asm("fma.rn.f32x2 %0, %1, %2, %3;" : "=l"(d) : "l"(a), "l"(b), "l"(c));
    return d;
}
__device__ __forceinline__ float2 unpack2(unsigned long long v) {
    float x, y;
    asm("mov.b64 {%0, %1}, %2;" : "=f"(x), "=f"(y) : "l"(v));
    return make_float2(x, y);
}
__device__ __forceinline__ float silu(float x) {
    return __fdividef(x, 1.0f + __expf(-x));
}
__device__ __forceinline__ void red_add_v4(float* p, float a, float b,
                                           float c, float d) {
    asm volatile("red.global.add.v4.f32 [%0], {%1, %2, %3, %4};"
                 :: "l"(p), "f"(a), "f"(b), "f"(c), "f"(d) : "memory");
}

// grid-wide barrier: all GRID blocks co-resident by construction
__device__ __forceinline__ void grid_sync(int p) {
    __syncthreads();
    if (threadIdx.x == 0) {
        __threadfence();
        unsigned arrived = atomicAdd(&g_bar[p], 1u) + 1u;
        if (arrived < GRID)
            while (*(volatile unsigned*)&g_bar[p] < GRID) {}
        __threadfence();
    }
    __syncthreads();
}

// ---------------------------------------------------------------------------
__device__ __forceinline__ void compute_ef_r(float r, float* ef) {
    float rs = fmaxf(r, 1e-9f);
    float t = r * 0.2f;
    if (t < 1.0f) {
        float t2 = t * t;
        float t5 = t2 * t2 * t;
        float env = 1.0f - 21.0f * t5 + 35.0f * t5 * t - 15.0f * t5 * t2;
        float scale = 0.6324555320336759f * env / rs;
        float x = 0.62831853071795864769f * rs;
        float s1, c1;
        __sincosf(x, &s1, &c1);
        float twoc = 2.0f * c1;
        float sm1 = 0.0f, sn = s1;
#pragma unroll
        for (int k = 0; k < NB; k++) {
            ef[k] = sn * scale;
            float nxt = twoc * sn - sm1;
            sm1 = sn; sn = nxt;
        }
    } else {
#pragma unroll
        for (int k = 0; k < NB; k++) ef[k] = 0.0f;
    }
}

// ---------------------------------------------------------------------------
// edge phase: 512 edges per block, 8 iterations x (64 edges x 8 slices)
// ---------------------------------------------------------------------------
__device__ __forceinline__ void edge_phase(const int* __restrict__ edge_index,
                                           const float* __restrict__ positions,
                                           int inter) {
    int tid = threadIdx.x;
    int s8 = (tid & 7) * 8;
#pragma unroll
    for (int ii = 0; ii < 8; ii++) {
        int e = blockIdx.x * 512 + ii * 64 + (tid >> 3);
        int snd = edge_index[e];
        int rcv = edge_index[N_EDGES + e];

        float r;
        if (inter == 0) {
            float dx = positions[rcv * 3 + 0] - positions[snd * 3 + 0];
            float dy = positions[rcv * 3 + 1] - positions[snd * 3 + 1];
            float dz = positions[rcv * 3 + 2] - positions[snd * 3 + 2];
            r = sqrtf(dx * dx + dy * dy + dz * dz);
            if ((tid & 7) == 0) g_r[e] = r;
        } else {
            r = g_r[e];
        }

        float u = r * ((float)TBL_N / 5.0f);
        int i0; float fr;
        if (u >= (float)TBL_N) { i0 = TBL_N - 1; fr = 1.0f; }
        else { i0 = (int)u; fr = u - (float)i0; }

        const float* tb = g_tbl + (inter * TBL_PTS + i0) * CDIM + s8;
        float4 a0 = *(const float4*)(tb);
        float4 a1 = *(const float4*)(tb + 4);
        float4 b0 = *(const float4*)(tb + CDIM);
        float4 b1 = *(const float4*)(tb + CDIM + 4);

        const float4* srow = (const float4*)(g_s + snd * CDIM + s8);
        float4 s0 = srow[0], s1 = srow[1];
        float* mrow = g_m + rcv * CDIM + s8;
        red_add_v4(mrow,
                   (a0.x + fr * (b0.x - a0.x)) * s0.x,
                   (a0.y + fr * (b0.y - a0.y)) * s0.y,
                   (a0.z + fr * (b0.z - a0.z)) * s0.z,
                   (a0.w + fr * (b0.w - a0.w)) * s0.w);
        red_add_v4(mrow + 4,
                   (a1.x + fr * (b1.x - a1.x)) * s1.x,
                   (a1.y + fr * (b1.y - a1.y)) * s1.y,
                   (a1.z + fr * (b1.z - a1.z)) * s1.z,
                   (a1.w + fr * (b1.w - a1.w)) * s1.w);
    }
}

// ---------------------------------------------------------------------------
// node phase: 64 nodes/block, 16 warps x 4 nodes (2 weight-sharing pairs)
// ---------------------------------------------------------------------------
__device__ __forceinline__ void node_phase(
    float* pool,
    const float* __restrict__ Wlin0, const float* __restrict__ Wprod,
    const float* __restrict__ Wsc, const float* __restrict__ Wread,
    const int* __restrict__ batch, float* __restrict__ d_out, int last) {
    float* swl = pool;               // 4096
    float* m_sm = pool + 4096;       // 4096
    float* bins = pool + 8192;       // 8

    int tid = threadIdx.x;
    for (int k = tid; k < 1024; k += THREADS)
        ((float4*)swl)[k] = ((const float4*)Wlin0)[k];

    float4* gm = (float4*)(g_m + blockIdx.x * NPB * CDIM);
#pragma unroll
    for (int q = 0; q < 2; q++) {
        int idx = q * THREADS + tid;
        float4 v = gm[idx];
        gm[idx] = make_float4(0.f, 0.f, 0.f, 0.f);
        ((float4*)m_sm)[idx] = make_float4(v.x * 0.125f, v.y * 0.125f,
                                           v.z * 0.125f, v.w * 0.125f);
    }
    if (tid < NGRAPH) bins[tid] = 0.0f;
    __syncthreads();

    int w = tid >> 5, g = tid & 31;
    int g2 = g * 2;

#pragma unroll
    for (int pair = 0; pair < 2; pair++) {
        int nl0 = w * 4 + pair * 2;
        const float* m0 = m_sm + nl0 * CDIM;
        const float* m1 = m0 + CDIM;
        unsigned long long acc0 = 0ull, acc1 = 0ull;
#pragma unroll 16
        for (int c = 0; c < CDIM; c++) {
            unsigned long long wv =
                *(const unsigned long long*)(swl + c * CDIM + g2);
            float av = m0[c], bv = m1[c];
            acc0 = ffma2(pack2(av, av), wv, acc0);
            acc1 = ffma2(pack2(bv, bv), wv, acc1);
        }
#pragma unroll
        for (int e = 0; e < 2; e++) {
            int node = blockIdx.x * NPB + nl0 + e;
            float2 f = unpack2(e ? acc1 : acc0);
            int el = g_elem[node];
            float2 w0 = *(const float2*)(Wprod + (0 * NELEM + el) * CDIM + g2);
            float2 w1 = *(const float2*)(Wprod + (1 * NELEM + el) * CDIM + g2);
            float2 w2 = *(const float2*)(Wprod + (2 * NELEM + el) * CDIM + g2);
            float2 sc = *(const float2*)(Wsc + el * CDIM + g2);
            float2 wr = *(const float2*)(Wread + g2);
            float2 sp = *(const float2*)(g_s + node * CDIM + g2);
            float hx = f.x * (w0.x + w1.x * f.x + w2.x * f.x * f.x) + sc.x * sp.x;
            float hy = f.y * (w0.y + w1.y * f.y + w2.y * f.y * f.y) + sc.y * sp.y;
            *(float2*)(g_s + node * CDIM + g2) = make_float2(hx, hy);
            float en = hx * wr.x + hy * wr.y;
#pragma unroll
            for (int off = 16; off > 0; off >>= 1)
                en += __shfl_down_sync(0xffffffffu, en, off);
            if (g == 0) {
                if (!last) g_energy[node] += en;
                else atomicAdd(&bins[batch[node]], g_energy[node] + en);
            }
        }
    }
    if (last) {
        __syncthreads();
        if (tid < NGRAPH) atomicAdd(d_out + tid, bins[tid]);
    }
}

// ---------------------------------------------------------------------------
// mega kernel: [init + table] -> edge0 -> node0 -> edge1 -> node1
// ---------------------------------------------------------------------------
__global__ __launch_bounds__(THREADS) void mega_kernel(
    const float* __restrict__ positions,
    const float* __restrict__ node_attrs,
    const int* __restrict__ edge_index,
    const int* __restrict__ batch,
    const float* __restrict__ atomic_energies,
    const float* __restrict__ W_embed,
    const float* __restrict__ rw1, const float* __restrict__ rb1,
    const float* __restrict__ rw2, const float* __restrict__ rb2,
    const float* __restrict__ rw3,
    const float* __restrict__ Wlin, const float* __restrict__ Wprod,
    const float* __restrict__ Wsc, const float* __restrict__ Wread,
    float* __restrict__ d_out) {
    __shared__ float pool[11076];    // 44.3 KB
    int tid = threadIdx.x;
    int bid = blockIdx.x;

    // ================= phase 0: init + table build =================
    {
        float* sw1 = pool;           // 512
        float* sw2 = pool + 512;     // 4096
        float* sw3 = pool + 4608;    // 4096
        float* sb1 = pool + 8704;    // 64
        float* sb2 = pool + 8768;    // 64
        float* act = pool + 8832;    // 33 * 68

        int i = bid >> 6;            // interaction for this block's table part
        const float* w1 = rw1 + i * NB * CDIM;
        const float* b1 = rb1 + i * CDIM;
        const float* w2 = rw2 + i * CDIM * CDIM;
        const float* b2 = rb2 + i * CDIM;
        const float* w3 = rw3 + i * CDIM * 4 * CDIM;

        for (int k = tid; k < 128; k += THREADS)
            ((float4*)sw1)[k] = ((const float4*)w1)[k];
        for (int k = tid; k < 1024; k += THREADS)
            ((float4*)sw2)[k] = ((const float4*)w2)[k];
        for (int k = tid; k < 1024; k += THREADS) {
            int c = k >> 4, jq = k & 15;     // l=0 slice of (64,256)
            ((float4*)sw3)[k] = ((const float4*)w3)[c * 64 + jq];
        }
        if (tid < CDIM) { sb1[tid] = b1[tid]; sb2[tid] = b2[tid]; }

        // init: threads 264..327 handle this block's 64 nodes
        if (tid >= 264 && tid < 264 + NPB) {
            int n = bid * NPB + (tid - 264);
            const float* row = node_attrs + n * NELEM;
            int el = 0;
#pragma unroll
            for (int k = 0; k < NELEM; k++)
                if (row[k] > 0.5f) el = k;
            g_elem[n] = el;
            g_energy[n] = atomic_energies[el];
            const float4* we = (const float4*)(W_embed + el * CDIM);
            float4* srow = (float4*)(g_s + n * CDIM);
            float4* mrow = (float4*)(g_m + n * CDIM);
#pragma unroll
            for (int q = 0; q < CDIM / 4; q++) {
                srow[q] = we[q];
                mrow[q] = make_float4(0.f, 0.f, 0.f, 0.f);
            }
        }
        if (bid == 0 && tid >= 328 && tid < 328 + NGRAPH)
            d_out[tid - 328] = 0.0f;
        __syncthreads();

        // table MLP: 8-thread slices; lp = local point 0..32
        int lp = tid >> 3;
        int s8 = (tid & 7) * 8;
        int pt = (bid & 63) * PPB + lp;
        bool on = (tid < PPB * 8) && (pt < TBL_PTS);

        float acc[8];
        if (on) {
            float r = (float)pt * (5.0f / (float)TBL_N);
            float ef[NB];
            compute_ef_r(r, ef);
            // layer 1: 8 -> 64 (this slice)
#pragma unroll
            for (int k = 0; k < 8; k++) acc[k] = sb1[s8 + k];
#pragma unroll
            for (int c = 0; c < NB; c++) {
                float x = ef[c];
                float4 wa = *(const float4*)(sw1 + c * CDIM + s8);
                float4 wb = *(const float4*)(sw1 + c * CDIM + s8 + 4);
                acc[0] += x * wa.x; acc[1] += x * wa.y;
                acc[2] += x * wa.z; acc[3] += x * wa.w;
                acc[4] += x * wb.x; acc[5] += x * wb.y;
                acc[6] += x * wb.z; acc[7] += x * wb.w;
            }
#pragma unroll
            for (int k = 0; k < 8; k++)
                act[lp * ACT_STRIDE + s8 + k] = silu(acc[k]);
        }
        __syncthreads();

        // layer 2
        if (on) {
#pragma unroll
            for (int k = 0; k < 8; k++) acc[k] = sb2[s8 + k];
            const float* arow = act + lp * ACT_STRIDE;
#pragma unroll 16
            for (int c = 0; c < CDIM; c++) {
                float x = arow[c];
                float4 wa = *(const float4*)(sw2 + c * CDIM + s8);
                float4 wb = *(const float4*)(sw2 + c * CDIM + s8 + 4);
                acc[0] += x * wa.x; acc[1] += x * wa.y;
                acc[2] += x * wa.z; acc[3] += x * wa.w;
                acc[4] += x * wb.x; acc[5] += x * wb.y;
                acc[6] += x * wb.z; acc[7] += x * wb.w;
            }
        }
        __syncthreads();
        if (on) {
#pragma unroll
            for (int k = 0; k < 8; k++)
                act[lp * ACT_STRIDE + s8 + k] = silu(acc[k]);
        }
        __syncthreads();

        // layer 3 + store
        if (on) {
#pragma unroll
            for (int k = 0; k < 8; k++) acc[k] = 0.0f;
            const float* arow = act + lp * ACT_STRIDE;
#pragma unroll 16
            for (int c = 0; c < CDIM; c++) {
                float x = arow[c];
                float4 wa = *(const float4*)(sw3 + c * CDIM + s8);
                float4 wb = *(const float4*)(sw3 + c * CDIM + s8 + 4);
                acc[0] += x * wa.x; acc[1] += x * wa.y;
                acc[2] += x * wa.z; acc[3] += x * wa.w;
                acc[4] += x * wb.x; acc[5] += x * wb.y;
                acc[6] += x * wb.z; acc[7] += x * wb.w;
            }
            float* dst = g_tbl + (i * TBL_PTS + pt) * CDIM + s8;
            *(float4*)(dst) = make_float4(acc[0], acc[1], acc[2], acc[3]);
            *(float4*)(dst + 4) = make_float4(acc[4], acc[5], acc[6], acc[7]);
        }
    }
    grid_sync(0);

    // ================= interaction 0 =================
    edge_phase(edge_index, positions, 0);
    grid_sync(1);
    node_phase(pool, Wlin, Wprod, Wsc, Wread, batch, d_out, 0);
    grid_sync(2);

    // ================= interaction 1 =================
    edge_phase(edge_index, positions, 1);
    grid_sync(3);
    node_phase(pool,
               Wlin + 4 * CDIM * CDIM,
               Wprod + 3 * NELEM * CDIM,
               Wsc + NELEM * CDIM,
               Wread + CDIM,
               batch, d_out, 1);

    // ================= exit + barrier reset (replay-safe) =================
    __syncthreads();
    if (tid == 0) {
        __threadfence();
        atomicAdd(&g_ack, 1u);
        if (bid == 0) {
            while (*(volatile unsigned*)&g_ack < GRID) {}
            g_bar[0] = 0; g_bar[1] = 0; g_bar[2] = 0; g_bar[3] = 0;
            *(volatile unsigned*)&g_ack = 0;
            __threadfence();
        }
    }
}

// ---------------------------------------------------------------------------
extern "C" void kernel_launch(void* const* d_in, const int* in_sizes, int n_in,
                              void* d_out, int out_size) {
    const float* positions       = (const float*)d_in[0];
    const float* node_attrs      = (const float*)d_in[1];
    const int*   edge_index      = (const int*)d_in[2];
    const int*   batch           = (const int*)d_in[3];
    const float* atomic_energies = (const float*)d_in[4];
    const float* W_embed         = (const float*)d_in[5];
    const float* rw1             = (const float*)d_in[6];
    const float* rb1             = (const float*)d_in[7];
    const float* rw2             = (const float*)d_in[8];
    const float* rb2             = (const float*)d_in[9];
    const float* rw3             = (const float*)d_in[10];
    const float* Wlin            = (const float*)d_in[11];
    const float* Wprod           = (const float*)d_in[12];
    const float* Wsc             = (const float*)d_in[13];
    const float* Wread           = (const float*)d_in[14];
    float* out = (float*)d_out;

    mega_kernel<<<GRID, THREADS>>>(positions, node_attrs, edge_index, batch,
                                   atomic_energies, W_embed,
                                   rw1, rb1, rw2, rb2, rw3,
                                   Wlin, Wprod, Wsc, Wread, out);
}

// round 14
// speedup vs baseline: 2.6832x; 1.0725x over previous
#include <cuda_runtime.h>
#include <math.h>

#define N_NODES 8192
#define N_EDGES 65536
#define CDIM 64
#define NB 8
#define NELEM 10
#define NGRAPH 8
#define TBL_N 2048
#define TBL_PTS (TBL_N + 1)
#define GRID 256
#define THREADS 512
#define NPB 32                      // nodes per block (8192/256)
#define EPBM 256                    // edges per block (65536/256)
#define PPB 17                      // table points per block per interaction
#define ACT_STRIDE 68               // padded act row

// Scratch (device globals; no allocation allowed)
__device__ float g_s[N_NODES * CDIM];
__device__ float g_m[N_NODES * CDIM];
__device__ float g_energy[N_NODES];
__device__ float g_r[N_EDGES];
__device__ int   g_elem[N_NODES];
__device__ float g_tbl[2 * TBL_PTS * CDIM];
__device__ unsigned g_bar[4];
__device__ unsigned g_ack;

// ---------------- packed f32x2 helpers -------------------------------------
__device__ __forceinline__ unsigned long long pack2(float x, float y) {
    unsigned long long r;
    asm("mov.b64 %0, {%1, %2};" : "=l"(r) : "f"(x), "f"(y));
    return r;
}
__device__ __forceinline__ unsigned long long ffma2(unsigned long long a,
                                                    unsigned long long b,
                                                    unsigned long long c) {
    unsigned long long d;
    asm("fma.rn.f32x2 %0, %1, %2, %3;" : "=l"(d) : "l"(a), "l"(b), "l"(c));
    return d;
}
__device__ __forceinline__ float2 unpack2(unsigned long long v) {
    float x, y;
    asm("mov.b64 {%0, %1}, %2;" : "=f"(x), "=f"(y) : "l"(v));
    return make_float2(x, y);
}
__device__ __forceinline__ float silu(float x) {
    return __fdividef(x, 1.0f + __expf(-x));
}
__device__ __forceinline__ void red_add_v4(float* p, float a, float b,
                                           float c, float d) {
    asm volatile("red.global.add.v4.f32 [%0], {%1, %2, %3, %4};"
                 :: "l"(p), "f"(a), "f"(b), "f"(c), "f"(d) : "memory");
}

// grid-wide barrier: all GRID blocks co-resident by construction
// (regs <= 64 via launch_bounds(512,2): 2*512*64 = 64K RF exact fit;
//  smem 2*40KB << 228KB; capacity 296 >= GRID=256)
__device__ __forceinline__ void grid_sync(int p) {
    __syncthreads();
    if (threadIdx.x == 0) {
        __threadfence();
        unsigned arrived = atomicAdd(&g_bar[p], 1u) + 1u;
        if (arrived < GRID)
            while (*(volatile unsigned*)&g_bar[p] < GRID) {}
        __threadfence();
    }
    __syncthreads();
}

// ---------------------------------------------------------------------------
__device__ __forceinline__ void compute_ef_r(float r, float* ef) {
    float rs = fmaxf(r, 1e-9f);
    float t = r * 0.2f;
    if (t < 1.0f) {
        float t2 = t * t;
        float t5 = t2 * t2 * t;
        float env = 1.0f - 21.0f * t5 + 35.0f * t5 * t - 15.0f * t5 * t2;
        float scale = 0.6324555320336759f * env / rs;
        float x = 0.62831853071795864769f * rs;
        float s1, c1;
        __sincosf(x, &s1, &c1);
        float twoc = 2.0f * c1;
        float sm1 = 0.0f, sn = s1;
#pragma unroll
        for (int k = 0; k < NB; k++) {
            ef[k] = sn * scale;
            float nxt = twoc * sn - sm1;
            sm1 = sn; sn = nxt;
        }
    } else {
#pragma unroll
        for (int k = 0; k < NB; k++) ef[k] = 0.0f;
    }
}

// ---------------------------------------------------------------------------
// edge phase: 256 edges per block, 4 iterations x (64 edges x 8 slices)
// ---------------------------------------------------------------------------
__device__ __forceinline__ void edge_phase(const int* __restrict__ edge_index,
                                           const float* __restrict__ positions,
                                           int inter) {
    int tid = threadIdx.x;
    int s8 = (tid & 7) * 8;
#pragma unroll
    for (int ii = 0; ii < 4; ii++) {
        int e = blockIdx.x * EPBM + ii * 64 + (tid >> 3);
        int snd = edge_index[e];
        int rcv = edge_index[N_EDGES + e];

        float r;
        if (inter == 0) {
            float dx = positions[rcv * 3 + 0] - positions[snd * 3 + 0];
            float dy = positions[rcv * 3 + 1] - positions[snd * 3 + 1];
            float dz = positions[rcv * 3 + 2] - positions[snd * 3 + 2];
            r = sqrtf(dx * dx + dy * dy + dz * dz);
            if ((tid & 7) == 0) g_r[e] = r;
        } else {
            r = g_r[e];
        }

        float u = r * ((float)TBL_N / 5.0f);
        int i0; float fr;
        if (u >= (float)TBL_N) { i0 = TBL_N - 1; fr = 1.0f; }
        else { i0 = (int)u; fr = u - (float)i0; }

        const float* tb = g_tbl + (inter * TBL_PTS + i0) * CDIM + s8;
        float4 a0 = *(const float4*)(tb);
        float4 a1 = *(const float4*)(tb + 4);
        float4 b0 = *(const float4*)(tb + CDIM);
        float4 b1 = *(const float4*)(tb + CDIM + 4);

        const float4* srow = (const float4*)(g_s + snd * CDIM + s8);
        float4 s0 = srow[0], s1 = srow[1];
        float* mrow = g_m + rcv * CDIM + s8;
        red_add_v4(mrow,
                   (a0.x + fr * (b0.x - a0.x)) * s0.x,
                   (a0.y + fr * (b0.y - a0.y)) * s0.y,
                   (a0.z + fr * (b0.z - a0.z)) * s0.z,
                   (a0.w + fr * (b0.w - a0.w)) * s0.w);
        red_add_v4(mrow + 4,
                   (a1.x + fr * (b1.x - a1.x)) * s1.x,
                   (a1.y + fr * (b1.y - a1.y)) * s1.y,
                   (a1.z + fr * (b1.z - a1.z)) * s1.z,
                   (a1.w + fr * (b1.w - a1.w)) * s1.w);
    }
}

// ---------------------------------------------------------------------------
// node phase: 32 nodes/block, 16 warps x 2 nodes (one weight-sharing pair)
// ---------------------------------------------------------------------------
__device__ __forceinline__ void node_phase(
    float* pool,
    const float* __restrict__ Wlin0, const float* __restrict__ Wprod,
    const float* __restrict__ Wsc, const float* __restrict__ Wread,
    const int* __restrict__ batch, float* __restrict__ d_out, int last) {
    float* swl = pool;               // 4096
    float* m_sm = pool + 4096;       // 2048
    float* bins = pool + 6144;       // 8

    int tid = threadIdx.x;
#pragma unroll
    for (int q = 0; q < 2; q++)
        ((float4*)swl)[q * THREADS + tid] =
            ((const float4*)Wlin0)[q * THREADS + tid];

    float4* gm = (float4*)(g_m + blockIdx.x * NPB * CDIM);
    {
        float4 v = gm[tid];
        gm[tid] = make_float4(0.f, 0.f, 0.f, 0.f);
        ((float4*)m_sm)[tid] = make_float4(v.x * 0.125f, v.y * 0.125f,
                                           v.z * 0.125f, v.w * 0.125f);
    }
    if (tid < NGRAPH) bins[tid] = 0.0f;
    __syncthreads();

    int w = tid >> 5, g = tid & 31;   // 16 warps x 2 nodes
    int g2 = g * 2;
    int nl0 = w * 2;
    const float* m0 = m_sm + nl0 * CDIM;
    const float* m1 = m0 + CDIM;
    unsigned long long acc0 = 0ull, acc1 = 0ull;
#pragma unroll 16
    for (int c = 0; c < CDIM; c++) {
        unsigned long long wv =
            *(const unsigned long long*)(swl + c * CDIM + g2);
        float av = m0[c], bv = m1[c];
        acc0 = ffma2(pack2(av, av), wv, acc0);
        acc1 = ffma2(pack2(bv, bv), wv, acc1);
    }
#pragma unroll
    for (int e = 0; e < 2; e++) {
        int node = blockIdx.x * NPB + nl0 + e;
        float2 f = unpack2(e ? acc1 : acc0);
        int el = g_elem[node];
        float2 w0 = *(const float2*)(Wprod + (0 * NELEM + el) * CDIM + g2);
        float2 w1 = *(const float2*)(Wprod + (1 * NELEM + el) * CDIM + g2);
        float2 w2 = *(const float2*)(Wprod + (2 * NELEM + el) * CDIM + g2);
        float2 sc = *(const float2*)(Wsc + el * CDIM + g2);
        float2 wr = *(const float2*)(Wread + g2);
        float2 sp = *(const float2*)(g_s + node * CDIM + g2);
        float hx = f.x * (w0.x + w1.x * f.x + w2.x * f.x * f.x) + sc.x * sp.x;
        float hy = f.y * (w0.y + w1.y * f.y + w2.y * f.y * f.y) + sc.y * sp.y;
        *(float2*)(g_s + node * CDIM + g2) = make_float2(hx, hy);
        float en = hx * wr.x + hy * wr.y;
#pragma unroll
        for (int off = 16; off > 0; off >>= 1)
            en += __shfl_down_sync(0xffffffffu, en, off);
        if (g == 0) {
            if (!last) g_energy[node] += en;
            else atomicAdd(&bins[batch[node]], g_energy[node] + en);
        }
    }
    if (last) {
        __syncthreads();
        if (tid < NGRAPH) atomicAdd(d_out + tid, bins[tid]);
    }
}

// ---------------------------------------------------------------------------
// mega kernel: [init + table] -> edge0 -> node0 -> edge1 -> node1
// ---------------------------------------------------------------------------
__global__ __launch_bounds__(THREADS, 2) void mega_kernel(
    const float* __restrict__ positions,
    const float* __restrict__ node_attrs,
    const int* __restrict__ edge_index,
    const int* __restrict__ batch,
    const float* __restrict__ atomic_energies,
    const float* __restrict__ W_embed,
    const float* __restrict__ rw1, const float* __restrict__ rb1,
    const float* __restrict__ rw2, const float* __restrict__ rb2,
    const float* __restrict__ rw3,
    const float* __restrict__ Wlin, const float* __restrict__ Wprod,
    const float* __restrict__ Wsc, const float* __restrict__ Wread,
    float* __restrict__ d_out) {
    __shared__ float pool[9988];     // ~40 KB
    int tid = threadIdx.x;
    int bid = blockIdx.x;

    // ================= phase 0: init + table build =================
    {
        float* sw1 = pool;           // 512
        float* sw2 = pool + 512;     // 4096
        float* sw3 = pool + 4608;    // 4096
        float* sb1 = pool + 8704;    // 64
        float* sb2 = pool + 8768;    // 64
        float* act = pool + 8832;    // 17 * 68 = 1156

        int i = bid >> 7;            // interaction (blocks 0-127 / 128-255)
        const float* w1 = rw1 + i * NB * CDIM;
        const float* b1 = rb1 + i * CDIM;
        const float* w2 = rw2 + i * CDIM * CDIM;
        const float* b2 = rb2 + i * CDIM;
        const float* w3 = rw3 + i * CDIM * 4 * CDIM;

        for (int k = tid; k < 128; k += THREADS)
            ((float4*)sw1)[k] = ((const float4*)w1)[k];
        for (int k = tid; k < 1024; k += THREADS)
            ((float4*)sw2)[k] = ((const float4*)w2)[k];
        for (int k = tid; k < 1024; k += THREADS) {
            int c = k >> 4, jq = k & 15;     // l=0 slice of (64,256)
            ((float4*)sw3)[k] = ((const float4*)w3)[c * 64 + jq];
        }
        if (tid < CDIM) { sb1[tid] = b1[tid]; sb2[tid] = b2[tid]; }

        // init: threads 160..191 handle this block's 32 nodes
        if (tid >= 160 && tid < 160 + NPB) {
            int n = bid * NPB + (tid - 160);
            const float* row = node_attrs + n * NELEM;
            int el = 0;
#pragma unroll
            for (int k = 0; k < NELEM; k++)
                if (row[k] > 0.5f) el = k;
            g_elem[n] = el;
            g_energy[n] = atomic_energies[el];
            const float4* we = (const float4*)(W_embed + el * CDIM);
            float4* srow = (float4*)(g_s + n * CDIM);
            float4* mrow = (float4*)(g_m + n * CDIM);
#pragma unroll
            for (int q = 0; q < CDIM / 4; q++) {
                srow[q] = we[q];
                mrow[q] = make_float4(0.f, 0.f, 0.f, 0.f);
            }
        }
        if (bid == 0 && tid >= 192 && tid < 192 + NGRAPH)
            d_out[tid - 192] = 0.0f;
        __syncthreads();

        // table MLP: 8-thread slices; lp = local point 0..16
        int lp = tid >> 3;
        int s8 = (tid & 7) * 8;
        int pt = (bid & 127) * PPB + lp;
        bool on = (tid < PPB * 8) && (pt < TBL_PTS);

        float acc[8];
        if (on) {
            float r = (float)pt * (5.0f / (float)TBL_N);
            float ef[NB];
            compute_ef_r(r, ef);
#pragma unroll
            for (int k = 0; k < 8; k++) acc[k] = sb1[s8 + k];
#pragma unroll
            for (int c = 0; c < NB; c++) {
                float x = ef[c];
                float4 wa = *(const float4*)(sw1 + c * CDIM + s8);
                float4 wb = *(const float4*)(sw1 + c * CDIM + s8 + 4);
                acc[0] += x * wa.x; acc[1] += x * wa.y;
                acc[2] += x * wa.z; acc[3] += x * wa.w;
                acc[4] += x * wb.x; acc[5] += x * wb.y;
                acc[6] += x * wb.z; acc[7] += x * wb.w;
            }
#pragma unroll
            for (int k = 0; k < 8; k++)
                act[lp * ACT_STRIDE + s8 + k] = silu(acc[k]);
        }
        __syncthreads();

        if (on) {
#pragma unroll
            for (int k = 0; k < 8; k++) acc[k] = sb2[s8 + k];
            const float* arow = act + lp * ACT_STRIDE;
#pragma unroll 16
            for (int c = 0; c < CDIM; c++) {
                float x = arow[c];
                float4 wa = *(const float4*)(sw2 + c * CDIM + s8);
                float4 wb = *(const float4*)(sw2 + c * CDIM + s8 + 4);
                acc[0] += x * wa.x; acc[1] += x * wa.y;
                acc[2] += x * wa.z; acc[3] += x * wa.w;
                acc[4] += x * wb.x; acc[5] += x * wb.y;
                acc[6] += x * wb.z; acc[7] += x * wb.w;
            }
        }
        __syncthreads();
        if (on) {
#pragma unroll
            for (int k = 0; k < 8; k++)
                act[lp * ACT_STRIDE + s8 + k] = silu(acc[k]);
        }
        __syncthreads();

        if (on) {
#pragma unroll
            for (int k = 0; k < 8; k++) acc[k] = 0.0f;
            const float* arow = act + lp * ACT_STRIDE;
#pragma unroll 16
            for (int c = 0; c < CDIM; c++) {
                float x = arow[c];
                float4 wa = *(const float4*)(sw3 + c * CDIM + s8);
                float4 wb = *(const float4*)(sw3 + c * CDIM + s8 + 4);
                acc[0] += x * wa.x; acc[1] += x * wa.y;
                acc[2] += x * wa.z; acc[3] += x * wa.w;
                acc[4] += x * wb.x; acc[5] += x * wb.y;
                acc[6] += x * wb.z; acc[7] += x * wb.w;
            }
            float* dst = g_tbl + (i * TBL_PTS + pt) * CDIM + s8;
            *(float4*)(dst) = make_float4(acc[0], acc[1], acc[2], acc[3]);
            *(float4*)(dst + 4) = make_float4(acc[4], acc[5], acc[6], acc[7]);
        }
    }
    grid_sync(0);

    // ================= interaction 0 =================
    edge_phase(edge_index, positions, 0);
    grid_sync(1);
    node_phase(pool, Wlin, Wprod, Wsc, Wread, batch, d_out, 0);
    grid_sync(2);

    // ================= interaction 1 =================
    edge_phase(edge_index, positions, 1);
    grid_sync(3);
    node_phase(pool,
               Wlin + 4 * CDIM * CDIM,
               Wprod + 3 * NELEM * CDIM,
               Wsc + NELEM * CDIM,
               Wread + CDIM,
               batch, d_out, 1);

    // ================= exit + barrier reset (replay-safe) =================
    __syncthreads();
    if (tid == 0) {
        __threadfence();
        atomicAdd(&g_ack, 1u);
        if (bid == 0) {
            while (*(volatile unsigned*)&g_ack < GRID) {}
            g_bar[0] = 0; g_bar[1] = 0; g_bar[2] = 0; g_bar[3] = 0;
            *(volatile unsigned*)&g_ack = 0;
            __threadfence();
        }
    }
}

// ---------------------------------------------------------------------------
extern "C" void kernel_launch(void* const* d_in, const int* in_sizes, int n_in,
                              void* d_out, int out_size) {
    const float* positions       = (const float*)d_in[0];
    const float* node_attrs      = (const float*)d_in[1];
    const int*   edge_index      = (const int*)d_in[2];
    const int*   batch           = (const int*)d_in[3];
    const float* atomic_energies = (const float*)d_in[4];
    const float* W_embed         = (const float*)d_in[5];
    const float* rw1             = (const float*)d_in[6];
    const float* rb1             = (const float*)d_in[7];
    const float* rw2             = (const float*)d_in[8];
    const float* rb2             = (const float*)d_in[9];
    const float* rw3             = (const float*)d_in[10];
    const float* Wlin            = (const float*)d_in[11];
    const float* Wprod           = (const float*)d_in[12];
    const float* Wsc             = (const float*)d_in[13];
    const float* Wread           = (const float*)d_in[14];
    float* out = (float*)d_out;

    mega_kernel<<<GRID, THREADS>>>(positions, node_attrs, edge_index, batch,
                                   atomic_energies, W_embed,
                                   rw1, rb1, rw2, rb2, rw3,
                                   Wlin, Wprod, Wsc, Wread, out);
}

// round 15
// speedup vs baseline: 2.7874x; 1.0388x over previous
#include <cuda_runtime.h>
#include <math.h>

#define N_NODES 8192
#define N_EDGES 65536
#define CDIM 64
#define NB 8
#define NELEM 10
#define NGRAPH 8
#define TBL_N 2048
#define TBL_PTS (TBL_N + 1)
#define GRID 128
#define THREADS 1024
#define NPB 64                      // nodes per block (8192/128)
#define PPB 17                      // table points per block per interaction
#define WB 8832                     // weight-block floats per interaction
#define ACT_OFF 17664
#define ACT_STRIDE 68
#define POOL_FLOATS (ACT_OFF + 2 * 20 * ACT_STRIDE)   // 20384 floats ~ 81.5KB

// Scratch (device globals; no allocation allowed)
__device__ float g_s[N_NODES * CDIM];
__device__ float g_m[N_NODES * CDIM];
__device__ float g_energy[N_NODES];
__device__ float g_r[N_EDGES];
__device__ int   g_elem[N_NODES];
__device__ float g_tbl[2 * TBL_PTS * CDIM];
__device__ unsigned g_bar[4];       // monotonically increasing across replays

// ---------------- packed f32x2 helpers -------------------------------------
__device__ __forceinline__ unsigned long long pack2(float x, float y) {
    unsigned long long r;
    asm("mov.b64 %0, {%1, %2};" : "=l"(r) : "f"(x), "f"(y));
    return r;
}
__device__ __forceinline__ unsigned long long ffma2(unsigned long long a,
                                                    unsigned long long b,
                                                    unsigned long long c) {
    unsigned long long d;
    asm("fma.rn.f32x2 %0, %1, %2, %3;" : "=l"(d) : "l"(a), "l"(b), "l"(c));
    return d;
}
__device__ __forceinline__ float2 unpack2(unsigned long long v) {
    float x, y;
    asm("mov.b64 {%0, %1}, %2;" : "=f"(x), "=f"(y) : "l"(v));
    return make_float2(x, y);
}
__device__ __forceinline__ float silu(float x) {
    return __fdividef(x, 1.0f + __expf(-x));
}
__device__ __forceinline__ void red_add_v4(float* p, float a, float b,
                                           float c, float d) {
    asm volatile("red.global.add.v4.f32 [%0], {%1, %2, %3, %4};"
                 :: "l"(p), "f"(a), "f"(b), "f"(c), "f"(d) : "memory");
}

// grid barrier: counter-based, NO reset needed (replay-safe by construction).
// All GRID blocks co-resident: 1 block/SM (1024 thr, <=64 regs, 81KB smem).
__device__ __forceinline__ void grid_sync(int p) {
    __syncthreads();
    if (threadIdx.x == 0) {
        __threadfence();
        unsigned old = atomicAdd(&g_bar[p], 1u);
        unsigned target = old - (old % GRID) + GRID;
        while (*(volatile unsigned*)&g_bar[p] < target) {}
        __threadfence();
    }
    __syncthreads();
}

// ---------------------------------------------------------------------------
__device__ __forceinline__ void compute_ef_r(float r, float* ef) {
    float rs = fmaxf(r, 1e-9f);
    float t = r * 0.2f;
    if (t < 1.0f) {
        float t2 = t * t;
        float t5 = t2 * t2 * t;
        float env = 1.0f - 21.0f * t5 + 35.0f * t5 * t - 15.0f * t5 * t2;
        float scale = 0.6324555320336759f * env / rs;
        float x = 0.62831853071795864769f * rs;
        float s1, c1;
        __sincosf(x, &s1, &c1);
        float twoc = 2.0f * c1;
        float sm1 = 0.0f, sn = s1;
#pragma unroll
        for (int k = 0; k < NB; k++) {
            ef[k] = sn * scale;
            float nxt = twoc * sn - sm1;
            sm1 = sn; sn = nxt;
        }
    } else {
#pragma unroll
        for (int k = 0; k < NB; k++) ef[k] = 0.0f;
    }
}

// ---------------------------------------------------------------------------
// edge phase: 512 edges/block, 4 passes x (128 edges x 8 slices)
// ---------------------------------------------------------------------------
__device__ __forceinline__ void edge_phase(const int* __restrict__ edge_index,
                                           const float* __restrict__ positions,
                                           int inter) {
    int tid = threadIdx.x;
    int s8 = (tid & 7) * 8;
#pragma unroll
    for (int ii = 0; ii < 4; ii++) {
        int e = blockIdx.x * 512 + ii * 128 + (tid >> 3);
        int snd = edge_index[e];
        int rcv = edge_index[N_EDGES + e];

        float r;
        if (inter == 0) {
            float dx = positions[rcv * 3 + 0] - positions[snd * 3 + 0];
            float dy = positions[rcv * 3 + 1] - positions[snd * 3 + 1];
            float dz = positions[rcv * 3 + 2] - positions[snd * 3 + 2];
            r = sqrtf(dx * dx + dy * dy + dz * dz);
            if ((tid & 7) == 0) g_r[e] = r;
        } else {
            r = g_r[e];
        }

        float u = r * ((float)TBL_N / 5.0f);
        int i0; float fr;
        if (u >= (float)TBL_N) { i0 = TBL_N - 1; fr = 1.0f; }
        else { i0 = (int)u; fr = u - (float)i0; }

        const float* tb = g_tbl + (inter * TBL_PTS + i0) * CDIM + s8;
        float4 a0 = *(const float4*)(tb);
        float4 a1 = *(const float4*)(tb + 4);
        float4 b0 = *(const float4*)(tb + CDIM);
        float4 b1 = *(const float4*)(tb + CDIM + 4);

        const float4* srow = (const float4*)(g_s + snd * CDIM + s8);
        float4 s0 = srow[0], s1 = srow[1];
        float* mrow = g_m + rcv * CDIM + s8;
        red_add_v4(mrow,
                   (a0.x + fr * (b0.x - a0.x)) * s0.x,
                   (a0.y + fr * (b0.y - a0.y)) * s0.y,
                   (a0.z + fr * (b0.z - a0.z)) * s0.z,
                   (a0.w + fr * (b0.w - a0.w)) * s0.w);
        red_add_v4(mrow + 4,
                   (a1.x + fr * (b1.x - a1.x)) * s1.x,
                   (a1.y + fr * (b1.y - a1.y)) * s1.y,
                   (a1.z + fr * (b1.z - a1.z)) * s1.z,
                   (a1.w + fr * (b1.w - a1.w)) * s1.w);
    }
}

// ---------------------------------------------------------------------------
// node phase: 64 nodes/block, 32 warps x 2 nodes
// ---------------------------------------------------------------------------
__device__ __forceinline__ void node_phase(
    float* pool,
    const float* __restrict__ Wlin0, const float* __restrict__ Wprod,
    const float* __restrict__ Wsc, const float* __restrict__ Wread,
    const int* __restrict__ batch, float* __restrict__ d_out, int last) {
    float* swl = pool;               // 4096
    float* m_sm = pool + 4096;       // 4096
    float* bins = pool + 8192;       // 8

    int tid = threadIdx.x;
    ((float4*)swl)[tid] = ((const float4*)Wlin0)[tid];

    float4* gm = (float4*)(g_m + blockIdx.x * NPB * CDIM);
    {
        float4 v = gm[tid];
        gm[tid] = make_float4(0.f, 0.f, 0.f, 0.f);
        ((float4*)m_sm)[tid] = make_float4(v.x * 0.125f, v.y * 0.125f,
                                           v.z * 0.125f, v.w * 0.125f);
    }
    if (tid < NGRAPH) bins[tid] = 0.0f;
    __syncthreads();

    int w = tid >> 5, g = tid & 31;   // 32 warps x 2 nodes
    int g2 = g * 2;
    int nl0 = w * 2;
    const float* m0 = m_sm + nl0 * CDIM;
    const float* m1 = m0 + CDIM;
    unsigned long long acc0 = 0ull, acc1 = 0ull;
#pragma unroll 16
    for (int c = 0; c < CDIM; c++) {
        unsigned long long wv =
            *(const unsigned long long*)(swl + c * CDIM + g2);
        float av = m0[c], bv = m1[c];
        acc0 = ffma2(pack2(av, av), wv, acc0);
        acc1 = ffma2(pack2(bv, bv), wv, acc1);
    }
#pragma unroll
    for (int e = 0; e < 2; e++) {
        int node = blockIdx.x * NPB + nl0 + e;
        float2 f = unpack2(e ? acc1 : acc0);
        int el = g_elem[node];
        float2 w0 = *(const float2*)(Wprod + (0 * NELEM + el) * CDIM + g2);
        float2 w1 = *(const float2*)(Wprod + (1 * NELEM + el) * CDIM + g2);
        float2 w2 = *(const float2*)(Wprod + (2 * NELEM + el) * CDIM + g2);
        float2 sc = *(const float2*)(Wsc + el * CDIM + g2);
        float2 wr = *(const float2*)(Wread + g2);
        float2 sp = *(const float2*)(g_s + node * CDIM + g2);
        float hx = f.x * (w0.x + w1.x * f.x + w2.x * f.x * f.x) + sc.x * sp.x;
        float hy = f.y * (w0.y + w1.y * f.y + w2.y * f.y * f.y) + sc.y * sp.y;
        *(float2*)(g_s + node * CDIM + g2) = make_float2(hx, hy);
        float en = hx * wr.x + hy * wr.y;
#pragma unroll
        for (int off = 16; off > 0; off >>= 1)
            en += __shfl_down_sync(0xffffffffu, en, off);
        if (g == 0) {
            if (!last) g_energy[node] += en;
            else atomicAdd(&bins[batch[node]], g_energy[node] + en);
        }
    }
    if (last) {
        __syncthreads();
        if (tid < NGRAPH) atomicAdd(d_out + tid, bins[tid]);
    }
}

// ---------------------------------------------------------------------------
// mega kernel: [init + both tables] -> edge0 -> node0 -> edge1 -> node1
// ---------------------------------------------------------------------------
__global__ __launch_bounds__(THREADS, 1) void mega_kernel(
    const float* __restrict__ positions,
    const float* __restrict__ node_attrs,
    const int* __restrict__ edge_index,
    const int* __restrict__ batch,
    const float* __restrict__ atomic_energies,
    const float* __restrict__ W_embed,
    const float* __restrict__ rw1, const float* __restrict__ rb1,
    const float* __restrict__ rw2, const float* __restrict__ rb2,
    const float* __restrict__ rw3,
    const float* __restrict__ Wlin, const float* __restrict__ Wprod,
    const float* __restrict__ Wsc, const float* __restrict__ Wread,
    float* __restrict__ d_out) {
    extern __shared__ float pool[];
    int tid = threadIdx.x;
    int bid = blockIdx.x;

    // ================= phase 0: init + BOTH tables in parallel =============
    {
        // stage both interactions' weights: pool[i*WB ...]
#pragma unroll
        for (int i = 0; i < 2; i++) {
            float* sw1 = pool + i * WB;
            float* sw2 = sw1 + 512;
            float* sw3 = sw2 + 4096;
            float* sb1 = sw3 + 4096;
            float* sb2 = sb1 + 64;
            const float* w1 = rw1 + i * NB * CDIM;
            const float* w2 = rw2 + i * CDIM * CDIM;
            const float* w3 = rw3 + i * CDIM * 4 * CDIM;
            for (int k = tid; k < 128; k += THREADS)
                ((float4*)sw1)[k] = ((const float4*)w1)[k];
            for (int k = tid; k < 1024; k += THREADS)
                ((float4*)sw2)[k] = ((const float4*)w2)[k];
            for (int k = tid; k < 1024; k += THREADS) {
                int c = k >> 4, jq = k & 15;     // l=0 slice of (64,256)
                ((float4*)sw3)[k] = ((const float4*)w3)[c * 64 + jq];
            }
            if (tid < CDIM) {
                sb1[tid] = rb1[i * CDIM + tid];
                sb2[tid] = rb2[i * CDIM + tid];
            }
        }

        // init: threads 320..383 handle this block's 64 nodes
        if (tid >= 320 && tid < 320 + NPB) {
            int n = bid * NPB + (tid - 320);
            const float* row = node_attrs + n * NELEM;
            int el = 0;
#pragma unroll
            for (int k = 0; k < NELEM; k++)
                if (row[k] > 0.5f) el = k;
            g_elem[n] = el;
            g_energy[n] = atomic_energies[el];
            const float4* we = (const float4*)(W_embed + el * CDIM);
            float4* srow = (float4*)(g_s + n * CDIM);
            float4* mrow = (float4*)(g_m + n * CDIM);
#pragma unroll
            for (int q = 0; q < CDIM / 4; q++) {
                srow[q] = we[q];
                mrow[q] = make_float4(0.f, 0.f, 0.f, 0.f);
            }
        }
        if (bid == 0 && tid >= 384 && tid < 384 + NGRAPH)
            d_out[tid - 384] = 0.0f;
        __syncthreads();

        // table MLP: warps 0-4 -> interaction 0, warps 5-9 -> interaction 1.
        // Point groups (8 threads) are warp-aligned -> __syncwarp only.
        int wid = tid >> 5;
        if (wid < 10) {
            int i = wid / 5;
            int local = tid - i * 160;        // 0..159
            int lp = local >> 3;              // 0..19
            int s8 = (local & 7) * 8;
            int pt = bid * PPB + lp;
            bool on = (lp < PPB) && (pt < TBL_PTS);

            float* sw1 = pool + i * WB;
            float* sw2 = sw1 + 512;
            float* sw3 = sw2 + 4096;
            float* sb1 = sw3 + 4096;
            float* sb2 = sb1 + 64;
            float* arow = pool + ACT_OFF + (i * 20 + lp) * ACT_STRIDE;

            float acc[8];
            if (on) {
                float r = (float)pt * (5.0f / (float)TBL_N);
                float ef[NB];
                compute_ef_r(r, ef);
#pragma unroll
                for (int k = 0; k < 8; k++) acc[k] = sb1[s8 + k];
#pragma unroll
                for (int c = 0; c < NB; c++) {
                    float x = ef[c];
                    float4 wa = *(const float4*)(sw1 + c * CDIM + s8);
                    float4 wb = *(const float4*)(sw1 + c * CDIM + s8 + 4);
                    acc[0] += x * wa.x; acc[1] += x * wa.y;
                    acc[2] += x * wa.z; acc[3] += x * wa.w;
                    acc[4] += x * wb.x; acc[5] += x * wb.y;
                    acc[6] += x * wb.z; acc[7] += x * wb.w;
                }
#pragma unroll
                for (int k = 0; k < 8; k++) arow[s8 + k] = silu(acc[k]);
            }
            __syncwarp();

            if (on) {
#pragma unroll
                for (int k = 0; k < 8; k++) acc[k] = sb2[s8 + k];
#pragma unroll 16
                for (int c = 0; c < CDIM; c++) {
                    float x = arow[c];
                    float4 wa = *(const float4*)(sw2 + c * CDIM + s8);
                    float4 wb = *(const float4*)(sw2 + c * CDIM + s8 + 4);
                    acc[0] += x * wa.x; acc[1] += x * wa.y;
                    acc[2] += x * wa.z; acc[3] += x * wa.w;
                    acc[4] += x * wb.x; acc[5] += x * wb.y;
                    acc[6] += x * wb.z; acc[7] += x * wb.w;
                }
            }
            __syncwarp();
            if (on) {
#pragma unroll
                for (int k = 0; k < 8; k++) arow[s8 + k] = silu(acc[k]);
            }
            __syncwarp();

            if (on) {
#pragma unroll
                for (int k = 0; k < 8; k++) acc[k] = 0.0f;
#pragma unroll 16
                for (int c = 0; c < CDIM; c++) {
                    float x = arow[c];
                    float4 wa = *(const float4*)(sw3 + c * CDIM + s8);
                    float4 wb = *(const float4*)(sw3 + c * CDIM + s8 + 4);
                    acc[0] += x * wa.x; acc[1] += x * wa.y;
                    acc[2] += x * wa.z; acc[3] += x * wa.w;
                    acc[4] += x * wb.x; acc[5] += x * wb.y;
                    acc[6] += x * wb.z; acc[7] += x * wb.w;
                }
                float* dst = g_tbl + (i * TBL_PTS + pt) * CDIM + s8;
                *(float4*)(dst) = make_float4(acc[0], acc[1], acc[2], acc[3]);
                *(float4*)(dst + 4) = make_float4(acc[4], acc[5], acc[6], acc[7]);
            }
        }
    }
    grid_sync(0);

    // ================= interaction 0 =================
    edge_phase(edge_index, positions, 0);
    grid_sync(1);
    node_phase(pool, Wlin, Wprod, Wsc, Wread, batch, d_out, 0);
    grid_sync(2);

    // ================= interaction 1 =================
    edge_phase(edge_index, positions, 1);
    grid_sync(3);
    node_phase(pool,
               Wlin + 4 * CDIM * CDIM,
               Wprod + 3 * NELEM * CDIM,
               Wsc + NELEM * CDIM,
               Wread + CDIM,
               batch, d_out, 1);
    // no reset needed: counter barriers are monotonic across replays
}

// ---------------------------------------------------------------------------
extern "C" void kernel_launch(void* const* d_in, const int* in_sizes, int n_in,
                              void* d_out, int out_size) {
    const float* positions       = (const float*)d_in[0];
    const float* node_attrs      = (const float*)d_in[1];
    const int*   edge_index      = (const int*)d_in[2];
    const int*   batch           = (const int*)d_in[3];
    const float* atomic_energies = (const float*)d_in[4];
    const float* W_embed         = (const float*)d_in[5];
    const float* rw1             = (const float*)d_in[6];
    const float* rb1             = (const float*)d_in[7];
    const float* rw2             = (const float*)d_in[8];
    const float* rb2             = (const float*)d_in[9];
    const float* rw3             = (const float*)d_in[10];
    const float* Wlin            = (const float*)d_in[11];
    const float* Wprod           = (const float*)d_in[12];
    const float* Wsc             = (const float*)d_in[13];
    const float* Wread           = (const float*)d_in[14];
    float* out = (float*)d_out;

    const int SMEM = POOL_FLOATS * 4;   // ~81.5 KB dynamic
    cudaFuncSetAttribute(mega_kernel,
                         cudaFuncAttributeMaxDynamicSharedMemorySize, SMEM);
    mega_kernel<<<GRID, THREADS, SMEM>>>(positions, node_attrs, edge_index,
                                         batch, atomic_energies, W_embed,
                                         rw1, rb1, rw2, rb2, rw3,
                                         Wlin, Wprod, Wsc, Wread, out);
}

// round 16
// speedup vs baseline: 2.8333x; 1.0165x over previous
#include <cuda_runtime.h>
#include <math.h>

#define N_NODES 8192
#define N_EDGES 65536
#define CDIM 64
#define NB 8
#define NELEM 10
#define NGRAPH 8
#define TBL_N 2048
#define TBL_PTS (TBL_N + 1)
#define GRID 128
#define THREADS 1024
#define NPB 64                      // nodes per block (8192/128)
#define PPB 17                      // table points per block per interaction
#define WB 8832                     // weight-block floats per interaction
#define ACT_OFF 17664
#define ACT_STRIDE 68
#define POOL_FLOATS (ACT_OFF + 2 * 20 * ACT_STRIDE)   // 20384 floats ~ 81.5KB

// Scratch (device globals; no allocation allowed)
__device__ float g_s[N_NODES * CDIM];
__device__ float g_m[N_NODES * CDIM];
__device__ float g_energy[N_NODES];
__device__ float g_r[N_EDGES];
__device__ int   g_elem[N_NODES];
__device__ float g_tbl[2 * TBL_PTS * CDIM];
__device__ unsigned g_bar[4];       // monotonically increasing across replays

// ---------------- packed f32x2 helpers -------------------------------------
__device__ __forceinline__ unsigned long long pack2(float x, float y) {
    unsigned long long r;
    asm("mov.b64 %0, {%1, %2};" : "=l"(r) : "f"(x), "f"(y));
    return r;
}
__device__ __forceinline__ unsigned long long ffma2(unsigned long long a,
                                                    unsigned long long b,
                                                    unsigned long long c) {
    unsigned long long d;
    asm("fma.rn.f32x2 %0, %1, %2, %3;" : "=l"(d) : "l"(a), "l"(b), "l"(c));
    return d;
}
__device__ __forceinline__ float2 unpack2(unsigned long long v) {
    float x, y;
    asm("mov.b64 {%0, %1}, %2;" : "=f"(x), "=f"(y) : "l"(v));
    return make_float2(x, y);
}
__device__ __forceinline__ float silu(float x) {
    return __fdividef(x, 1.0f + __expf(-x));
}
__device__ __forceinline__ void red_add_v4(float* p, float a, float b,
                                           float c, float d) {
    asm volatile("red.global.add.v4.f32 [%0], {%1, %2, %3, %4};"
                 :: "l"(p), "f"(a), "f"(b), "f"(c), "f"(d) : "memory");
}

// grid barrier: counter-based, NO reset needed (replay-safe by construction).
// All GRID blocks co-resident: 1 block/SM (1024 thr, <=64 regs, 81KB smem).
__device__ __forceinline__ void grid_sync(int p) {
    __syncthreads();
    if (threadIdx.x == 0) {
        __threadfence();
        unsigned old = atomicAdd(&g_bar[p], 1u);
        unsigned target = old - (old % GRID) + GRID;
        while (*(volatile unsigned*)&g_bar[p] < target) {}
        __threadfence();
    }
    __syncthreads();
}

// ---------------------------------------------------------------------------
__device__ __forceinline__ void compute_ef_r(float r, float* ef) {
    float rs = fmaxf(r, 1e-9f);
    float t = r * 0.2f;
    if (t < 1.0f) {
        float t2 = t * t;
        float t5 = t2 * t2 * t;
        float env = 1.0f - 21.0f * t5 + 35.0f * t5 * t - 15.0f * t5 * t2;
        float scale = 0.6324555320336759f * env / rs;
        float x = 0.62831853071795864769f * rs;
        float s1, c1;
        __sincosf(x, &s1, &c1);
        float twoc = 2.0f * c1;
        float sm1 = 0.0f, sn = s1;
#pragma unroll
        for (int k = 0; k < NB; k++) {
            ef[k] = sn * scale;
            float nxt = twoc * sn - sm1;
            sm1 = sn; sn = nxt;
        }
    } else {
#pragma unroll
        for (int k = 0; k < NB; k++) ef[k] = 0.0f;
    }
}

// ---------------------------------------------------------------------------
// edge phase: 512 edges/block; each 8-thread slice-group owns 4 CONSECUTIVE
// edges -> indices via 2x int4 + r via 1x float4 (group-uniform broadcast),
// so all 4 table/s chains are independent and start immediately.
// ---------------------------------------------------------------------------
__device__ __forceinline__ void edge_phase(const int* __restrict__ edge_index,
                                           const float* __restrict__ positions,
                                           int inter) {
    int tid = threadIdx.x;
    int s8 = (tid & 7) * 8;
    int e_base = blockIdx.x * 512 + (tid >> 3) * 4;

    int4 snd4 = __ldg((const int4*)(edge_index + e_base));
    int4 rcv4 = __ldg((const int4*)(edge_index + N_EDGES + e_base));
    const int* snds = &snd4.x;
    const int* rcvs = &rcv4.x;

    float r4[4];
    if (inter == 0) {
#pragma unroll
        for (int e = 0; e < 4; e++) {
            int sn = snds[e], rc = rcvs[e];
            float dx = __ldg(positions + rc * 3 + 0) - __ldg(positions + sn * 3 + 0);
            float dy = __ldg(positions + rc * 3 + 1) - __ldg(positions + sn * 3 + 1);
            float dz = __ldg(positions + rc * 3 + 2) - __ldg(positions + sn * 3 + 2);
            r4[e] = sqrtf(dx * dx + dy * dy + dz * dz);
        }
        if ((tid & 7) == 0)
            *(float4*)(g_r + e_base) = make_float4(r4[0], r4[1], r4[2], r4[3]);
    } else {
        float4 rv = *(const float4*)(g_r + e_base);
        r4[0] = rv.x; r4[1] = rv.y; r4[2] = rv.z; r4[3] = rv.w;
    }

#pragma unroll
    for (int e = 0; e < 4; e++) {
        float u = r4[e] * ((float)TBL_N / 5.0f);
        int i0; float fr;
        if (u >= (float)TBL_N) { i0 = TBL_N - 1; fr = 1.0f; }
        else { i0 = (int)u; fr = u - (float)i0; }

        const float* tb = g_tbl + (inter * TBL_PTS + i0) * CDIM + s8;
        float4 a0 = __ldg((const float4*)(tb));
        float4 a1 = __ldg((const float4*)(tb + 4));
        float4 b0 = __ldg((const float4*)(tb + CDIM));
        float4 b1 = __ldg((const float4*)(tb + CDIM + 4));

        const float4* srow = (const float4*)(g_s + snds[e] * CDIM + s8);
        float4 s0 = srow[0], s1 = srow[1];
        float* mrow = g_m + rcvs[e] * CDIM + s8;
        red_add_v4(mrow,
                   (a0.x + fr * (b0.x - a0.x)) * s0.x,
                   (a0.y + fr * (b0.y - a0.y)) * s0.y,
                   (a0.z + fr * (b0.z - a0.z)) * s0.z,
                   (a0.w + fr * (b0.w - a0.w)) * s0.w);
        red_add_v4(mrow + 4,
                   (a1.x + fr * (b1.x - a1.x)) * s1.x,
                   (a1.y + fr * (b1.y - a1.y)) * s1.y,
                   (a1.z + fr * (b1.z - a1.z)) * s1.z,
                   (a1.w + fr * (b1.w - a1.w)) * s1.w);
    }
}

// ---------------------------------------------------------------------------
// node phase: 64 nodes/block, 32 warps x 2 nodes
// ---------------------------------------------------------------------------
__device__ __forceinline__ void node_phase(
    float* pool,
    const float* __restrict__ Wlin0, const float* __restrict__ Wprod,
    const float* __restrict__ Wsc, const float* __restrict__ Wread,
    const int* __restrict__ batch, float* __restrict__ d_out, int last) {
    float* swl = pool;               // 4096
    float* m_sm = pool + 4096;       // 4096
    float* bins = pool + 8192;       // 8

    int tid = threadIdx.x;
    ((float4*)swl)[tid] = ((const float4*)Wlin0)[tid];

    float4* gm = (float4*)(g_m + blockIdx.x * NPB * CDIM);
    {
        float4 v = gm[tid];
        gm[tid] = make_float4(0.f, 0.f, 0.f, 0.f);
        ((float4*)m_sm)[tid] = make_float4(v.x * 0.125f, v.y * 0.125f,
                                           v.z * 0.125f, v.w * 0.125f);
    }
    if (tid < NGRAPH) bins[tid] = 0.0f;
    __syncthreads();

    int w = tid >> 5, g = tid & 31;   // 32 warps x 2 nodes
    int g2 = g * 2;
    int nl0 = w * 2;
    const float* m0 = m_sm + nl0 * CDIM;
    const float* m1 = m0 + CDIM;
    unsigned long long acc0 = 0ull, acc1 = 0ull;
#pragma unroll 16
    for (int c = 0; c < CDIM; c++) {
        unsigned long long wv =
            *(const unsigned long long*)(swl + c * CDIM + g2);
        float av = m0[c], bv = m1[c];
        acc0 = ffma2(pack2(av, av), wv, acc0);
        acc1 = ffma2(pack2(bv, bv), wv, acc1);
    }
#pragma unroll
    for (int e = 0; e < 2; e++) {
        int node = blockIdx.x * NPB + nl0 + e;
        float2 f = unpack2(e ? acc1 : acc0);
        int el = g_elem[node];
        float2 w0 = *(const float2*)(Wprod + (0 * NELEM + el) * CDIM + g2);
        float2 w1 = *(const float2*)(Wprod + (1 * NELEM + el) * CDIM + g2);
        float2 w2 = *(const float2*)(Wprod + (2 * NELEM + el) * CDIM + g2);
        float2 sc = *(const float2*)(Wsc + el * CDIM + g2);
        float2 wr = *(const float2*)(Wread + g2);
        float2 sp = *(const float2*)(g_s + node * CDIM + g2);
        float hx = f.x * (w0.x + w1.x * f.x + w2.x * f.x * f.x) + sc.x * sp.x;
        float hy = f.y * (w0.y + w1.y * f.y + w2.y * f.y * f.y) + sc.y * sp.y;
        *(float2*)(g_s + node * CDIM + g2) = make_float2(hx, hy);
        float en = hx * wr.x + hy * wr.y;
#pragma unroll
        for (int off = 16; off > 0; off >>= 1)
            en += __shfl_down_sync(0xffffffffu, en, off);
        if (g == 0) {
            if (!last) g_energy[node] += en;
            else atomicAdd(&bins[batch[node]], g_energy[node] + en);
        }
    }
    if (last) {
        __syncthreads();
        if (tid < NGRAPH) atomicAdd(d_out + tid, bins[tid]);
    }
}

// ---------------------------------------------------------------------------
// mega kernel: [init + both tables] -> edge0 -> node0 -> edge1 -> node1
// ---------------------------------------------------------------------------
__global__ __launch_bounds__(THREADS, 1) void mega_kernel(
    const float* __restrict__ positions,
    const float* __restrict__ node_attrs,
    const int* __restrict__ edge_index,
    const int* __restrict__ batch,
    const float* __restrict__ atomic_energies,
    const float* __restrict__ W_embed,
    const float* __restrict__ rw1, const float* __restrict__ rb1,
    const float* __restrict__ rw2, const float* __restrict__ rb2,
    const float* __restrict__ rw3,
    const float* __restrict__ Wlin, const float* __restrict__ Wprod,
    const float* __restrict__ Wsc, const float* __restrict__ Wread,
    float* __restrict__ d_out) {
    extern __shared__ float pool[];
    int tid = threadIdx.x;
    int bid = blockIdx.x;

    // ================= phase 0: init + BOTH tables in parallel =============
    {
#pragma unroll
        for (int i = 0; i < 2; i++) {
            float* sw1 = pool + i * WB;
            float* sw2 = sw1 + 512;
            float* sw3 = sw2 + 4096;
            float* sb1 = sw3 + 4096;
            float* sb2 = sb1 + 64;
            const float* w1 = rw1 + i * NB * CDIM;
            const float* w2 = rw2 + i * CDIM * CDIM;
            const float* w3 = rw3 + i * CDIM * 4 * CDIM;
            for (int k = tid; k < 128; k += THREADS)
                ((float4*)sw1)[k] = ((const float4*)w1)[k];
            for (int k = tid; k < 1024; k += THREADS)
                ((float4*)sw2)[k] = ((const float4*)w2)[k];
            for (int k = tid; k < 1024; k += THREADS) {
                int c = k >> 4, jq = k & 15;     // l=0 slice of (64,256)
                ((float4*)sw3)[k] = ((const float4*)w3)[c * 64 + jq];
            }
            if (tid < CDIM) {
                sb1[tid] = rb1[i * CDIM + tid];
                sb2[tid] = rb2[i * CDIM + tid];
            }
        }

        // init: threads 320..383 handle this block's 64 nodes
        if (tid >= 320 && tid < 320 + NPB) {
            int n = bid * NPB + (tid - 320);
            const float* row = node_attrs + n * NELEM;
            int el = 0;
#pragma unroll
            for (int k = 0; k < NELEM; k++)
                if (row[k] > 0.5f) el = k;
            g_elem[n] = el;
            g_energy[n] = atomic_energies[el];
            const float4* we = (const float4*)(W_embed + el * CDIM);
            float4* srow = (float4*)(g_s + n * CDIM);
            float4* mrow = (float4*)(g_m + n * CDIM);
#pragma unroll
            for (int q = 0; q < CDIM / 4; q++) {
                srow[q] = we[q];
                mrow[q] = make_float4(0.f, 0.f, 0.f, 0.f);
            }
        }
        if (bid == 0 && tid >= 384 && tid < 384 + NGRAPH)
            d_out[tid - 384] = 0.0f;
        __syncthreads();

        // table MLP: warps 0-4 -> interaction 0, warps 5-9 -> interaction 1.
        int wid = tid >> 5;
        if (wid < 10) {
            int i = wid / 5;
            int local = tid - i * 160;        // 0..159
            int lp = local >> 3;              // 0..19
            int s8 = (local & 7) * 8;
            int pt = bid * PPB + lp;
            bool on = (lp < PPB) && (pt < TBL_PTS);

            float* sw1 = pool + i * WB;
            float* sw2 = sw1 + 512;
            float* sw3 = sw2 + 4096;
            float* sb1 = sw3 + 4096;
            float* sb2 = sb1 + 64;
            float* arow = pool + ACT_OFF + (i * 20 + lp) * ACT_STRIDE;

            float acc[8];
            if (on) {
                float r = (float)pt * (5.0f / (float)TBL_N);
                float ef[NB];
                compute_ef_r(r, ef);
#pragma unroll
                for (int k = 0; k < 8; k++) acc[k] = sb1[s8 + k];
#pragma unroll
                for (int c = 0; c < NB; c++) {
                    float x = ef[c];
                    float4 wa = *(const float4*)(sw1 + c * CDIM + s8);
                    float4 wb = *(const float4*)(sw1 + c * CDIM + s8 + 4);
                    acc[0] += x * wa.x; acc[1] += x * wa.y;
                    acc[2] += x * wa.z; acc[3] += x * wa.w;
                    acc[4] += x * wb.x; acc[5] += x * wb.y;
                    acc[6] += x * wb.z; acc[7] += x * wb.w;
                }
#pragma unroll
                for (int k = 0; k < 8; k++) arow[s8 + k] = silu(acc[k]);
            }
            __syncwarp();

            if (on) {
#pragma unroll
                for (int k = 0; k < 8; k++) acc[k] = sb2[s8 + k];
#pragma unroll 16
                for (int c = 0; c < CDIM; c++) {
                    float x = arow[c];
                    float4 wa = *(const float4*)(sw2 + c * CDIM + s8);
                    float4 wb = *(const float4*)(sw2 + c * CDIM + s8 + 4);
                    acc[0] += x * wa.x; acc[1] += x * wa.y;
                    acc[2] += x * wa.z; acc[3] += x * wa.w;
                    acc[4] += x * wb.x; acc[5] += x * wb.y;
                    acc[6] += x * wb.z; acc[7] += x * wb.w;
                }
            }
            __syncwarp();
            if (on) {
#pragma unroll
                for (int k = 0; k < 8; k++) arow[s8 + k] = silu(acc[k]);
            }
            __syncwarp();

            if (on) {
#pragma unroll
                for (int k = 0; k < 8; k++) acc[k] = 0.0f;
#pragma unroll 16
                for (int c = 0; c < CDIM; c++) {
                    float x = arow[c];
                    float4 wa = *(const float4*)(sw3 + c * CDIM + s8);
                    float4 wb = *(const float4*)(sw3 + c * CDIM + s8 + 4);
                    acc[0] += x * wa.x; acc[1] += x * wa.y;
                    acc[2] += x * wa.z; acc[3] += x * wa.w;
                    acc[4] += x * wb.x; acc[5] += x * wb.y;
                    acc[6] += x * wb.z; acc[7] += x * wb.w;
                }
                float* dst = g_tbl + (i * TBL_PTS + pt) * CDIM + s8;
                *(float4*)(dst) = make_float4(acc[0], acc[1], acc[2], acc[3]);
                *(float4*)(dst + 4) = make_float4(acc[4], acc[5], acc[6], acc[7]);
            }
        }
    }
    grid_sync(0);

    // ================= interaction 0 =================
    edge_phase(edge_index, positions, 0);
    grid_sync(1);
    node_phase(pool, Wlin, Wprod, Wsc, Wread, batch, d_out, 0);
    grid_sync(2);

    // ================= interaction 1 =================
    edge_phase(edge_index, positions, 1);
    grid_sync(3);
    node_phase(pool,
               Wlin + 4 * CDIM * CDIM,
               Wprod + 3 * NELEM * CDIM,
               Wsc + NELEM * CDIM,
               Wread + CDIM,
               batch, d_out, 1);
    // no reset needed: counter barriers are monotonic across replays
}

// ---------------------------------------------------------------------------
extern "C" void kernel_launch(void* const* d_in, const int* in_sizes, int n_in,
                              void* d_out, int out_size) {
    const float* positions       = (const float*)d_in[0];
    const float* node_attrs      = (const float*)d_in[1];
    const int*   edge_index      = (const int*)d_in[2];
    const int*   batch           = (const int*)d_in[3];
    const float* atomic_energies = (const float*)d_in[4];
    const float* W_embed         = (const float*)d_in[5];
    const float* rw1             = (const float*)d_in[6];
    const float* rb1             = (const float*)d_in[7];
    const float* rw2             = (const float*)d_in[8];
    const float* rb2             = (const float*)d_in[9];
    const float* rw3             = (const float*)d_in[10];
    const float* Wlin            = (const float*)d_in[11];
    const float* Wprod           = (const float*)d_in[12];
    const float* Wsc             = (const float*)d_in[13];
    const float* Wread           = (const float*)d_in[14];
    float* out = (float*)d_out;

    const int SMEM = POOL_FLOATS * 4;   // ~81.5 KB dynamic
    cudaFuncSetAttribute(mega_kernel,
                         cudaFuncAttributeMaxDynamicSharedMemorySize, SMEM);
    mega_kernel<<<GRID, THREADS, SMEM>>>(positions, node_attrs, edge_index,
                                         batch, atomic_energies, W_embed,
                                         rw1, rb1, rw2, rb2, rw3,
                                         Wlin, Wprod, Wsc, Wread, out);
}